// round 1
// baseline (speedup 1.0000x reference)
#include <cuda_runtime.h>
#include <math.h>

#define BQ 4
#define TQ 2048
#define EQ 1024
#define HQ 16
#define DQ 64
// SCALE = 1/sqrt(64) = 0.125 exactly

// Scratch (allocation-free rule: __device__ globals)
__device__ float g_qkv[(size_t)BQ * TQ * 3 * EQ];  // [8192, 3072]
__device__ float g_y[(size_t)BQ * TQ * EQ];        // [8192, 1024]

// ---------------------------------------------------------------------------
// SGEMM + bias: C[M,N] = A[M,K] @ W[K,N] + bias[N]
// 128x128 block tile, BK=8, 256 threads, 8x8 register micro-tile.
// M % 128 == 0, N % 128 == 0, K % 8 == 0 (holds for all three shapes here).
// ---------------------------------------------------------------------------
__global__ __launch_bounds__(256) void sgemm_bias_kernel(
    const float* __restrict__ A, const float* __restrict__ W,
    const float* __restrict__ bias, float* __restrict__ C,
    int M, int N, int K)
{
    __shared__ float As[8][128];   // transposed A tile
    __shared__ float Bs[8][128];

    const int tid = threadIdx.x;
    const int bm = blockIdx.y * 128;
    const int bn = blockIdx.x * 128;
    const int tr = tid >> 4;    // 0..15 -> rows tr*8..tr*8+7
    const int tc = tid & 15;    // 0..15 -> cols tc*8..tc*8+7

    const int a_row = tid >> 1;         // 0..127
    const int a_col = (tid & 1) * 4;    // 0 or 4
    const int b_row = tid >> 5;         // 0..7
    const int b_col = (tid & 31) * 4;   // 0..124

    const float* Ap = A + (size_t)(bm + a_row) * K + a_col;
    const float* Wp = W + (size_t)b_row * N + bn + b_col;

    float acc[8][8];
    #pragma unroll
    for (int i = 0; i < 8; i++)
        #pragma unroll
        for (int j = 0; j < 8; j++) acc[i][j] = 0.f;

    for (int k0 = 0; k0 < K; k0 += 8) {
        float4 av = *(const float4*)(Ap + k0);
        As[a_col + 0][a_row] = av.x;
        As[a_col + 1][a_row] = av.y;
        As[a_col + 2][a_row] = av.z;
        As[a_col + 3][a_row] = av.w;
        float4 wv = *(const float4*)(Wp + (size_t)k0 * N);
        *(float4*)&Bs[b_row][b_col] = wv;
        __syncthreads();

        #pragma unroll
        for (int k = 0; k < 8; k++) {
            float ra[8], rb[8];
            #pragma unroll
            for (int i = 0; i < 8; i++) ra[i] = As[k][tr * 8 + i];
            *(float4*)&rb[0] = *(const float4*)&Bs[k][tc * 8];
            *(float4*)&rb[4] = *(const float4*)&Bs[k][tc * 8 + 4];
            #pragma unroll
            for (int i = 0; i < 8; i++)
                #pragma unroll
                for (int j = 0; j < 8; j++)
                    acc[i][j] += ra[i] * rb[j];
        }
        __syncthreads();
    }

    #pragma unroll
    for (int i = 0; i < 8; i++) {
        float* Cp = C + (size_t)(bm + tr * 8 + i) * N + bn + tc * 8;
        #pragma unroll
        for (int j = 0; j < 8; j += 4) {
            float4 v;
            v.x = acc[i][j + 0] + bias[bn + tc * 8 + j + 0];
            v.y = acc[i][j + 1] + bias[bn + tc * 8 + j + 1];
            v.z = acc[i][j + 2] + bias[bn + tc * 8 + j + 2];
            v.w = acc[i][j + 3] + bias[bn + tc * 8 + j + 3];
            *(float4*)(Cp + j) = v;
        }
    }
}

// ---------------------------------------------------------------------------
// Flash attention (causal), fp32.
// grid: (T/64, H, B), 256 threads. 64x64 Q/K/V tiles, 4x4 register micro-tile.
// Q/K/V read directly from fused qkv buffer [B*T, 3E].
// Dynamic smem: Qs/Ks/Vs/Ps each 64x65 floats = 66560 B total.
// ---------------------------------------------------------------------------
__global__ __launch_bounds__(256) void flash_attn_kernel(
    const float* __restrict__ qkv, float* __restrict__ y)
{
    extern __shared__ float smem[];
    float (*Qs)[65] = (float(*)[65])(smem);
    float (*Ks)[65] = (float(*)[65])(smem + 64 * 65);
    float (*Vs)[65] = (float(*)[65])(smem + 2 * 64 * 65);
    float (*Ps)[65] = (float(*)[65])(smem + 3 * 64 * 65);

    const int qt = blockIdx.x;   // query tile
    const int h  = blockIdx.y;
    const int b  = blockIdx.z;
    const int tid = threadIdx.x;
    const int tr = tid >> 4;     // 0..15 -> rows tr*4..+4
    const int tc = tid & 15;     // 0..15 -> cols tc*4..+4

    const int lrow = tid >> 2;          // 0..63 (loader row)
    const int lcol = (tid & 3) * 16;    // loader col base

    const size_t rs = 3 * EQ;           // qkv row stride

    // Load Q tile (pre-scaled by 1/sqrt(D))
    {
        const float* src = qkv + ((size_t)(b * TQ) + qt * 64 + lrow) * rs + h * DQ + lcol;
        #pragma unroll
        for (int i = 0; i < 16; i += 4) {
            float4 v = *(const float4*)(src + i);
            Qs[lrow][lcol + i + 0] = v.x * 0.125f;
            Qs[lrow][lcol + i + 1] = v.y * 0.125f;
            Qs[lrow][lcol + i + 2] = v.z * 0.125f;
            Qs[lrow][lcol + i + 3] = v.w * 0.125f;
        }
    }

    float m[4], l[4], o[4][4];
    #pragma unroll
    for (int i = 0; i < 4; i++) {
        m[i] = -1e30f;
        l[i] = 0.f;
        #pragma unroll
        for (int j = 0; j < 4; j++) o[i][j] = 0.f;
    }

    for (int jt = 0; jt <= qt; jt++) {
        __syncthreads();  // Qs ready (iter 0); prior Vs/Ps reads done (iter>0)
        // Load K and V tiles
        {
            const float* ksrc = qkv + ((size_t)(b * TQ) + jt * 64 + lrow) * rs + EQ + h * DQ + lcol;
            const float* vsrc = ksrc + EQ;
            #pragma unroll
            for (int i = 0; i < 16; i += 4) {
                float4 kv = *(const float4*)(ksrc + i);
                Ks[lrow][lcol + i + 0] = kv.x;
                Ks[lrow][lcol + i + 1] = kv.y;
                Ks[lrow][lcol + i + 2] = kv.z;
                Ks[lrow][lcol + i + 3] = kv.w;
                float4 vv = *(const float4*)(vsrc + i);
                Vs[lrow][lcol + i + 0] = vv.x;
                Vs[lrow][lcol + i + 1] = vv.y;
                Vs[lrow][lcol + i + 2] = vv.z;
                Vs[lrow][lcol + i + 3] = vv.w;
            }
        }
        __syncthreads();

        // S = Q K^T for this thread's 4x4 micro-tile
        float s[4][4];
        #pragma unroll
        for (int i = 0; i < 4; i++)
            #pragma unroll
            for (int j = 0; j < 4; j++) s[i][j] = 0.f;

        #pragma unroll 16
        for (int d = 0; d < 64; d++) {
            float qa[4], kb[4];
            #pragma unroll
            for (int i = 0; i < 4; i++) qa[i] = Qs[tr * 4 + i][d];
            #pragma unroll
            for (int j = 0; j < 4; j++) kb[j] = Ks[tc * 4 + j][d];
            #pragma unroll
            for (int i = 0; i < 4; i++)
                #pragma unroll
                for (int j = 0; j < 4; j++)
                    s[i][j] += qa[i] * kb[j];
        }

        // Causal mask on diagonal tile
        if (jt == qt) {
            #pragma unroll
            for (int i = 0; i < 4; i++)
                #pragma unroll
                for (int j = 0; j < 4; j++)
                    if (tc * 4 + j > tr * 4 + i) s[i][j] = -1e30f;
        }

        // Online softmax per row (row owned by 16 consecutive lanes)
        #pragma unroll
        for (int i = 0; i < 4; i++) {
            float mt = fmaxf(fmaxf(s[i][0], s[i][1]), fmaxf(s[i][2], s[i][3]));
            mt = fmaxf(mt, __shfl_xor_sync(0xffffffffu, mt, 1));
            mt = fmaxf(mt, __shfl_xor_sync(0xffffffffu, mt, 2));
            mt = fmaxf(mt, __shfl_xor_sync(0xffffffffu, mt, 4));
            mt = fmaxf(mt, __shfl_xor_sync(0xffffffffu, mt, 8));
            float mnew = fmaxf(m[i], mt);
            float alpha = __expf(m[i] - mnew);
            float psum = 0.f;
            #pragma unroll
            for (int j = 0; j < 4; j++) {
                float p = __expf(s[i][j] - mnew);
                Ps[tr * 4 + i][tc * 4 + j] = p;
                psum += p;
            }
            psum += __shfl_xor_sync(0xffffffffu, psum, 1);
            psum += __shfl_xor_sync(0xffffffffu, psum, 2);
            psum += __shfl_xor_sync(0xffffffffu, psum, 4);
            psum += __shfl_xor_sync(0xffffffffu, psum, 8);
            l[i] = l[i] * alpha + psum;
            m[i] = mnew;
            #pragma unroll
            for (int j = 0; j < 4; j++) o[i][j] *= alpha;
        }
        __syncthreads();

        // O += P V   (thread owns rows tr*4..+4, d-cols tc*4..+4)
        #pragma unroll 16
        for (int c = 0; c < 64; c++) {
            float pv[4], vv[4];
            #pragma unroll
            for (int i = 0; i < 4; i++) pv[i] = Ps[tr * 4 + i][c];
            #pragma unroll
            for (int j = 0; j < 4; j++) vv[j] = Vs[c][tc * 4 + j];
            #pragma unroll
            for (int i = 0; i < 4; i++)
                #pragma unroll
                for (int j = 0; j < 4; j++)
                    o[i][j] += pv[i] * vv[j];
        }
    }

    // Write y[b, t, h*D + d]
    #pragma unroll
    for (int i = 0; i < 4; i++) {
        float inv = 1.f / l[i];
        float4 v;
        v.x = o[i][0] * inv;
        v.y = o[i][1] * inv;
        v.z = o[i][2] * inv;
        v.w = o[i][3] * inv;
        float* dst = g_y + ((size_t)(b * TQ) + qt * 64 + tr * 4 + i) * EQ + h * DQ + tc * 4;
        *(float4*)dst = v;
    }
    (void)y;
}

// ---------------------------------------------------------------------------
extern "C" void kernel_launch(void* const* d_in, const int* in_sizes, int n_in,
                              void* d_out, int out_size)
{
    const float* x     = (const float*)d_in[0];
    const float* Wqkv  = (const float*)d_in[1];
    const float* bqkv  = (const float*)d_in[2];
    const float* Wproj = (const float*)d_in[3];
    const float* bproj = (const float*)d_in[4];
    float* out = (float*)d_out;

    float* qkv = nullptr;
    float* y = nullptr;
    cudaGetSymbolAddress((void**)&qkv, g_qkv);
    cudaGetSymbolAddress((void**)&y, g_y);

    const int M = BQ * TQ;  // 8192

    // 1) QKV GEMM: [8192,1024] @ [1024,3072] + b
    {
        dim3 grid(3 * EQ / 128, M / 128);
        sgemm_bias_kernel<<<grid, 256>>>(x, Wqkv, bqkv, qkv, M, 3 * EQ, EQ);
    }

    // 2) Flash attention -> g_y
    {
        const int smem_bytes = 4 * 64 * 65 * (int)sizeof(float);  // 66560
        cudaFuncSetAttribute(flash_attn_kernel,
                             cudaFuncAttributeMaxDynamicSharedMemorySize, smem_bytes);
        dim3 grid(TQ / 64, HQ, BQ);
        flash_attn_kernel<<<grid, 256, smem_bytes>>>(qkv, y);
    }

    // 3) Proj GEMM: [8192,1024] @ [1024,1024] + b -> d_out
    {
        dim3 grid(EQ / 128, M / 128);
        sgemm_bias_kernel<<<grid, 256>>>(y, Wproj, bproj, out, M, EQ, EQ);
    }

    (void)in_sizes; (void)n_in; (void)out_size;
}

// round 2
// speedup vs baseline: 1.6024x; 1.6024x over previous
#include <cuda_runtime.h>
#include <math.h>
#include <stdint.h>

#define BQ 4
#define TQ 2048
#define EQ 1024
#define HQ 16
#define DQ 64

// Scratch (allocation-free rule: __device__ globals)
__device__ float g_qkv[(size_t)BQ * TQ * 3 * EQ];  // [8192, 3072]
__device__ float g_y[(size_t)BQ * TQ * EQ];        // [8192, 1024]

// ---------------------------------------------------------------------------
// helpers
// ---------------------------------------------------------------------------
__device__ __forceinline__ uint32_t smem_u32(const void* p) {
    return (uint32_t)__cvta_generic_to_shared(p);
}

__device__ __forceinline__ void cp16(uint32_t dst, const void* src) {
    asm volatile("cp.async.cg.shared.global [%0], [%1], 16;\n" ::"r"(dst), "l"(src));
}

__device__ __forceinline__ void cp_commit() {
    asm volatile("cp.async.commit_group;\n");
}

template <int N>
__device__ __forceinline__ void cp_wait() {
    asm volatile("cp.async.wait_group %0;\n" ::"n"(N));
}

__device__ __forceinline__ uint32_t f2tf32(float f) {
    uint32_t u;
    asm("cvt.rna.tf32.f32 %0, %1;\n" : "=r"(u) : "f"(f));
    return u;
}

__device__ __forceinline__ void mma_tf32(float* c, const uint32_t* a, const uint32_t* b) {
    asm volatile(
        "mma.sync.aligned.m16n8k8.row.col.f32.tf32.tf32.f32 "
        "{%0,%1,%2,%3},{%4,%5,%6,%7},{%8,%9},{%0,%1,%2,%3};\n"
        : "+f"(c[0]), "+f"(c[1]), "+f"(c[2]), "+f"(c[3])
        : "r"(a[0]), "r"(a[1]), "r"(a[2]), "r"(a[3]), "r"(b[0]), "r"(b[1]));
}

// ---------------------------------------------------------------------------
// tf32 tensor-core GEMM + bias: C[M,N] = A[M,K] @ W[K,N] + bias[N]
// 128x128 block tile, TILE_K=16, 256 threads (8 warps, 4x2 warp grid,
// each warp 32x64). cp.async double-buffered. M%128==0, N%128==0, K%16==0.
// ---------------------------------------------------------------------------
#define GK 16
#define ASTRIDE 20   // 16 + 4 pad: fragment loads conflict-free
#define BSTRIDE 136  // 128 + 8 pad: fragment loads conflict-free

__global__ __launch_bounds__(256) void gemm_tf32_bias_kernel(
    const float* __restrict__ A, const float* __restrict__ W,
    const float* __restrict__ bias, float* __restrict__ C,
    int M, int N, int K)
{
    __shared__ float As[2][128][ASTRIDE];
    __shared__ float Bs[2][GK][BSTRIDE];

    const int tid  = threadIdx.x;
    const int lane = tid & 31;
    const int warp = tid >> 5;
    const int wm   = (warp >> 1) * 32;  // warp row offset in tile
    const int wn   = (warp & 1) * 64;   // warp col offset in tile
    const int g    = lane >> 2;         // group id 0..7
    const int q    = lane & 3;          // quad id 0..3

    const int bm = blockIdx.y * 128;
    const int bn = blockIdx.x * 128;

    float acc[2][8][4];
    #pragma unroll
    for (int i = 0; i < 2; i++)
        #pragma unroll
        for (int j = 0; j < 8; j++)
            #pragma unroll
            for (int r = 0; r < 4; r++) acc[i][j][r] = 0.f;

    const int nt = K / GK;

    // prologue: load tile 0 into buf 0
    {
        #pragma unroll
        for (int i = 0; i < 2; i++) {
            int j = tid + i * 256;               // 0..511
            int row = j >> 2, c4 = (j & 3) * 4;  // row 0..127, col {0,4,8,12}
            cp16(smem_u32(&As[0][row][c4]), A + (size_t)(bm + row) * K + c4);
        }
        #pragma unroll
        for (int i = 0; i < 2; i++) {
            int j = tid + i * 256;
            int kr = j >> 5, nc = (j & 31) * 4;  // kr 0..15, nc 0..124
            cp16(smem_u32(&Bs[0][kr][nc]), W + (size_t)kr * N + bn + nc);
        }
        cp_commit();
    }

    for (int kt = 0; kt < nt; kt++) {
        const int buf = kt & 1;
        // issue loads for next tile into other buffer
        if (kt + 1 < nt) {
            const int nb = buf ^ 1;
            const int k0 = (kt + 1) * GK;
            #pragma unroll
            for (int i = 0; i < 2; i++) {
                int j = tid + i * 256;
                int row = j >> 2, c4 = (j & 3) * 4;
                cp16(smem_u32(&As[nb][row][c4]), A + (size_t)(bm + row) * K + k0 + c4);
            }
            #pragma unroll
            for (int i = 0; i < 2; i++) {
                int j = tid + i * 256;
                int kr = j >> 5, nc = (j & 31) * 4;
                cp16(smem_u32(&Bs[nb][kr][nc]), W + (size_t)(k0 + kr) * N + bn + nc);
            }
            cp_commit();
            cp_wait<1>();
        } else {
            cp_wait<0>();
        }
        __syncthreads();

        // compute on buf: two k-substeps of 8
        #pragma unroll
        for (int ks = 0; ks < GK; ks += 8) {
            uint32_t afr[2][4];
            #pragma unroll
            for (int i = 0; i < 2; i++) {
                int r0 = wm + i * 16 + g;
                afr[i][0] = f2tf32(As[buf][r0][ks + q]);
                afr[i][1] = f2tf32(As[buf][r0 + 8][ks + q]);
                afr[i][2] = f2tf32(As[buf][r0][ks + q + 4]);
                afr[i][3] = f2tf32(As[buf][r0 + 8][ks + q + 4]);
            }
            uint32_t bfr[8][2];
            #pragma unroll
            for (int j = 0; j < 8; j++) {
                int n0 = wn + j * 8 + g;
                bfr[j][0] = f2tf32(Bs[buf][ks + q][n0]);
                bfr[j][1] = f2tf32(Bs[buf][ks + q + 4][n0]);
            }
            #pragma unroll
            for (int i = 0; i < 2; i++)
                #pragma unroll
                for (int j = 0; j < 8; j++)
                    mma_tf32(acc[i][j], afr[i], bfr[j]);
        }
        __syncthreads();  // all reads of buf done before it is refilled
    }

    // epilogue: C = acc + bias
    #pragma unroll
    for (int i = 0; i < 2; i++) {
        #pragma unroll
        for (int j = 0; j < 8; j++) {
            int row = bm + wm + i * 16 + g;
            int col = bn + wn + j * 8 + 2 * q;
            float bx = bias[col], by = bias[col + 1];
            float2 v0 = make_float2(acc[i][j][0] + bx, acc[i][j][1] + by);
            float2 v1 = make_float2(acc[i][j][2] + bx, acc[i][j][3] + by);
            *(float2*)(C + (size_t)row * N + col) = v0;
            *(float2*)(C + (size_t)(row + 8) * N + col) = v1;
        }
    }
}

// ---------------------------------------------------------------------------
// Flash attention (causal), fp32 SIMT (unchanged from round 1).
// grid: (T/64, H, B), 256 threads. 64x64 tiles, 4x4 register micro-tile.
// ---------------------------------------------------------------------------
__global__ __launch_bounds__(256) void flash_attn_kernel(
    const float* __restrict__ qkv, float* __restrict__ y)
{
    extern __shared__ float smem[];
    float (*Qs)[65] = (float(*)[65])(smem);
    float (*Ks)[65] = (float(*)[65])(smem + 64 * 65);
    float (*Vs)[65] = (float(*)[65])(smem + 2 * 64 * 65);
    float (*Ps)[65] = (float(*)[65])(smem + 3 * 64 * 65);

    const int qt = blockIdx.x;
    const int h  = blockIdx.y;
    const int b  = blockIdx.z;
    const int tid = threadIdx.x;
    const int tr = tid >> 4;
    const int tc = tid & 15;

    const int lrow = tid >> 2;
    const int lcol = (tid & 3) * 16;

    const size_t rs = 3 * EQ;

    {
        const float* src = qkv + ((size_t)(b * TQ) + qt * 64 + lrow) * rs + h * DQ + lcol;
        #pragma unroll
        for (int i = 0; i < 16; i += 4) {
            float4 v = *(const float4*)(src + i);
            Qs[lrow][lcol + i + 0] = v.x * 0.125f;
            Qs[lrow][lcol + i + 1] = v.y * 0.125f;
            Qs[lrow][lcol + i + 2] = v.z * 0.125f;
            Qs[lrow][lcol + i + 3] = v.w * 0.125f;
        }
    }

    float m[4], l[4], o[4][4];
    #pragma unroll
    for (int i = 0; i < 4; i++) {
        m[i] = -1e30f;
        l[i] = 0.f;
        #pragma unroll
        for (int j = 0; j < 4; j++) o[i][j] = 0.f;
    }

    for (int jt = 0; jt <= qt; jt++) {
        __syncthreads();
        {
            const float* ksrc = qkv + ((size_t)(b * TQ) + jt * 64 + lrow) * rs + EQ + h * DQ + lcol;
            const float* vsrc = ksrc + EQ;
            #pragma unroll
            for (int i = 0; i < 16; i += 4) {
                float4 kv = *(const float4*)(ksrc + i);
                Ks[lrow][lcol + i + 0] = kv.x;
                Ks[lrow][lcol + i + 1] = kv.y;
                Ks[lrow][lcol + i + 2] = kv.z;
                Ks[lrow][lcol + i + 3] = kv.w;
                float4 vv = *(const float4*)(vsrc + i);
                Vs[lrow][lcol + i + 0] = vv.x;
                Vs[lrow][lcol + i + 1] = vv.y;
                Vs[lrow][lcol + i + 2] = vv.z;
                Vs[lrow][lcol + i + 3] = vv.w;
            }
        }
        __syncthreads();

        float s[4][4];
        #pragma unroll
        for (int i = 0; i < 4; i++)
            #pragma unroll
            for (int j = 0; j < 4; j++) s[i][j] = 0.f;

        #pragma unroll 16
        for (int d = 0; d < 64; d++) {
            float qa[4], kb[4];
            #pragma unroll
            for (int i = 0; i < 4; i++) qa[i] = Qs[tr * 4 + i][d];
            #pragma unroll
            for (int j = 0; j < 4; j++) kb[j] = Ks[tc * 4 + j][d];
            #pragma unroll
            for (int i = 0; i < 4; i++)
                #pragma unroll
                for (int j = 0; j < 4; j++)
                    s[i][j] += qa[i] * kb[j];
        }

        if (jt == qt) {
            #pragma unroll
            for (int i = 0; i < 4; i++)
                #pragma unroll
                for (int j = 0; j < 4; j++)
                    if (tc * 4 + j > tr * 4 + i) s[i][j] = -1e30f;
        }

        #pragma unroll
        for (int i = 0; i < 4; i++) {
            float mt = fmaxf(fmaxf(s[i][0], s[i][1]), fmaxf(s[i][2], s[i][3]));
            mt = fmaxf(mt, __shfl_xor_sync(0xffffffffu, mt, 1));
            mt = fmaxf(mt, __shfl_xor_sync(0xffffffffu, mt, 2));
            mt = fmaxf(mt, __shfl_xor_sync(0xffffffffu, mt, 4));
            mt = fmaxf(mt, __shfl_xor_sync(0xffffffffu, mt, 8));
            float mnew = fmaxf(m[i], mt);
            float alpha = __expf(m[i] - mnew);
            float psum = 0.f;
            #pragma unroll
            for (int j = 0; j < 4; j++) {
                float p = __expf(s[i][j] - mnew);
                Ps[tr * 4 + i][tc * 4 + j] = p;
                psum += p;
            }
            psum += __shfl_xor_sync(0xffffffffu, psum, 1);
            psum += __shfl_xor_sync(0xffffffffu, psum, 2);
            psum += __shfl_xor_sync(0xffffffffu, psum, 4);
            psum += __shfl_xor_sync(0xffffffffu, psum, 8);
            l[i] = l[i] * alpha + psum;
            m[i] = mnew;
            #pragma unroll
            for (int j = 0; j < 4; j++) o[i][j] *= alpha;
        }
        __syncthreads();

        #pragma unroll 16
        for (int c = 0; c < 64; c++) {
            float pv[4], vv[4];
            #pragma unroll
            for (int i = 0; i < 4; i++) pv[i] = Ps[tr * 4 + i][c];
            #pragma unroll
            for (int j = 0; j < 4; j++) vv[j] = Vs[c][tc * 4 + j];
            #pragma unroll
            for (int i = 0; i < 4; i++)
                #pragma unroll
                for (int j = 0; j < 4; j++)
                    o[i][j] += pv[i] * vv[j];
        }
    }

    #pragma unroll
    for (int i = 0; i < 4; i++) {
        float inv = 1.f / l[i];
        float4 v;
        v.x = o[i][0] * inv;
        v.y = o[i][1] * inv;
        v.z = o[i][2] * inv;
        v.w = o[i][3] * inv;
        float* dst = g_y + ((size_t)(b * TQ) + qt * 64 + tr * 4 + i) * EQ + h * DQ + tc * 4;
        *(float4*)dst = v;
    }
    (void)y;
}

// ---------------------------------------------------------------------------
extern "C" void kernel_launch(void* const* d_in, const int* in_sizes, int n_in,
                              void* d_out, int out_size)
{
    const float* x     = (const float*)d_in[0];
    const float* Wqkv  = (const float*)d_in[1];
    const float* bqkv  = (const float*)d_in[2];
    const float* Wproj = (const float*)d_in[3];
    const float* bproj = (const float*)d_in[4];
    float* out = (float*)d_out;

    float* qkv = nullptr;
    float* y = nullptr;
    cudaGetSymbolAddress((void**)&qkv, g_qkv);
    cudaGetSymbolAddress((void**)&y, g_y);

    const int M = BQ * TQ;  // 8192

    // 1) QKV GEMM (tf32 tensor cores): [8192,1024] @ [1024,3072] + b
    {
        dim3 grid(3 * EQ / 128, M / 128);
        gemm_tf32_bias_kernel<<<grid, 256>>>(x, Wqkv, bqkv, qkv, M, 3 * EQ, EQ);
    }

    // 2) Flash attention -> g_y
    {
        const int smem_bytes = 4 * 64 * 65 * (int)sizeof(float);  // 66560
        cudaFuncSetAttribute(flash_attn_kernel,
                             cudaFuncAttributeMaxDynamicSharedMemorySize, smem_bytes);
        dim3 grid(TQ / 64, HQ, BQ);
        flash_attn_kernel<<<grid, 256, smem_bytes>>>(qkv, y);
    }

    // 3) Proj GEMM (tf32 tensor cores): [8192,1024] @ [1024,1024] + b -> d_out
    {
        dim3 grid(EQ / 128, M / 128);
        gemm_tf32_bias_kernel<<<grid, 256>>>(y, Wproj, bproj, out, M, EQ, EQ);
    }

    (void)in_sizes; (void)n_in; (void)out_size;
}

// round 6
// speedup vs baseline: 2.5175x; 1.5711x over previous
#include <cuda_runtime.h>
#include <math.h>
#include <stdint.h>

#define BQ 4
#define TQ 2048
#define EQ 1024
#define HQ 16
#define DQ 64

// Scratch (allocation-free rule: __device__ globals)
__device__ float g_qkv[(size_t)BQ * TQ * 3 * EQ];  // [8192, 3072]
__device__ float g_y[(size_t)BQ * TQ * EQ];        // [8192, 1024]

// ---------------------------------------------------------------------------
// helpers
// ---------------------------------------------------------------------------
__device__ __forceinline__ uint32_t smem_u32(const void* p) {
    return (uint32_t)__cvta_generic_to_shared(p);
}

__device__ __forceinline__ void cp16(uint32_t dst, const void* src) {
    asm volatile("cp.async.cg.shared.global [%0], [%1], 16;\n" ::"r"(dst), "l"(src));
}

__device__ __forceinline__ void cp_commit() {
    asm volatile("cp.async.commit_group;\n");
}

template <int N>
__device__ __forceinline__ void cp_wait() {
    asm volatile("cp.async.wait_group %0;\n" ::"n"(N));
}

__device__ __forceinline__ uint32_t f2tf32(float f) {
    uint32_t u;
    asm("cvt.rna.tf32.f32 %0, %1;\n" : "=r"(u) : "f"(f));
    return u;
}

__device__ __forceinline__ void mma_tf32(float* c, const uint32_t* a, const uint32_t* b) {
    asm volatile(
        "mma.sync.aligned.m16n8k8.row.col.f32.tf32.tf32.f32 "
        "{%0,%1,%2,%3},{%4,%5,%6,%7},{%8,%9},{%0,%1,%2,%3};\n"
        : "+f"(c[0]), "+f"(c[1]), "+f"(c[2]), "+f"(c[3])
        : "r"(a[0]), "r"(a[1]), "r"(a[2]), "r"(a[3]), "r"(b[0]), "r"(b[1]));
}

// ---------------------------------------------------------------------------
// tf32 tensor-core GEMM + bias (unchanged from round 2)
// ---------------------------------------------------------------------------
#define GK 16
#define ASTRIDE 20
#define BSTRIDE 136

__global__ __launch_bounds__(256) void gemm_tf32_bias_kernel(
    const float* __restrict__ A, const float* __restrict__ W,
    const float* __restrict__ bias, float* __restrict__ C,
    int M, int N, int K)
{
    __shared__ float As[2][128][ASTRIDE];
    __shared__ float Bs[2][GK][BSTRIDE];

    const int tid  = threadIdx.x;
    const int lane = tid & 31;
    const int warp = tid >> 5;
    const int wm   = (warp >> 1) * 32;
    const int wn   = (warp & 1) * 64;
    const int g    = lane >> 2;
    const int q    = lane & 3;

    const int bm = blockIdx.y * 128;
    const int bn = blockIdx.x * 128;

    float acc[2][8][4];
    #pragma unroll
    for (int i = 0; i < 2; i++)
        #pragma unroll
        for (int j = 0; j < 8; j++)
            #pragma unroll
            for (int r = 0; r < 4; r++) acc[i][j][r] = 0.f;

    const int nt = K / GK;

    {
        #pragma unroll
        for (int i = 0; i < 2; i++) {
            int j = tid + i * 256;
            int row = j >> 2, c4 = (j & 3) * 4;
            cp16(smem_u32(&As[0][row][c4]), A + (size_t)(bm + row) * K + c4);
        }
        #pragma unroll
        for (int i = 0; i < 2; i++) {
            int j = tid + i * 256;
            int kr = j >> 5, nc = (j & 31) * 4;
            cp16(smem_u32(&Bs[0][kr][nc]), W + (size_t)kr * N + bn + nc);
        }
        cp_commit();
    }

    for (int kt = 0; kt < nt; kt++) {
        const int buf = kt & 1;
        if (kt + 1 < nt) {
            const int nb = buf ^ 1;
            const int k0 = (kt + 1) * GK;
            #pragma unroll
            for (int i = 0; i < 2; i++) {
                int j = tid + i * 256;
                int row = j >> 2, c4 = (j & 3) * 4;
                cp16(smem_u32(&As[nb][row][c4]), A + (size_t)(bm + row) * K + k0 + c4);
            }
            #pragma unroll
            for (int i = 0; i < 2; i++) {
                int j = tid + i * 256;
                int kr = j >> 5, nc = (j & 31) * 4;
                cp16(smem_u32(&Bs[nb][kr][nc]), W + (size_t)(k0 + kr) * N + bn + nc);
            }
            cp_commit();
            cp_wait<1>();
        } else {
            cp_wait<0>();
        }
        __syncthreads();

        #pragma unroll
        for (int ks = 0; ks < GK; ks += 8) {
            uint32_t afr[2][4];
            #pragma unroll
            for (int i = 0; i < 2; i++) {
                int r0 = wm + i * 16 + g;
                afr[i][0] = f2tf32(As[buf][r0][ks + q]);
                afr[i][1] = f2tf32(As[buf][r0 + 8][ks + q]);
                afr[i][2] = f2tf32(As[buf][r0][ks + q + 4]);
                afr[i][3] = f2tf32(As[buf][r0 + 8][ks + q + 4]);
            }
            uint32_t bfr[8][2];
            #pragma unroll
            for (int j = 0; j < 8; j++) {
                int n0 = wn + j * 8 + g;
                bfr[j][0] = f2tf32(Bs[buf][ks + q][n0]);
                bfr[j][1] = f2tf32(Bs[buf][ks + q + 4][n0]);
            }
            #pragma unroll
            for (int i = 0; i < 2; i++)
                #pragma unroll
                for (int j = 0; j < 8; j++)
                    mma_tf32(acc[i][j], afr[i], bfr[j]);
        }
        __syncthreads();
    }

    #pragma unroll
    for (int i = 0; i < 2; i++) {
        #pragma unroll
        for (int j = 0; j < 8; j++) {
            int row = bm + wm + i * 16 + g;
            int col = bn + wn + j * 8 + 2 * q;
            float bx = bias[col], by = bias[col + 1];
            float2 v0 = make_float2(acc[i][j][0] + bx, acc[i][j][1] + by);
            float2 v1 = make_float2(acc[i][j][2] + bx, acc[i][j][3] + by);
            *(float2*)(C + (size_t)row * N + col) = v0;
            *(float2*)(C + (size_t)(row + 8) * N + col) = v1;
        }
    }
}

// ---------------------------------------------------------------------------
// Flash attention (causal) on tensor cores, tf32 MMA.
// Block: 128 q-rows x D=64, 8 warps (each m16). KV tiles 64 wide,
// cp.async double-buffered. QK^T uses split-tf32 (3 MMAs) for accuracy;
// PV plain tf32. Smem stride 68 -> S-phase fragment loads conflict-free.
// ---------------------------------------------------------------------------
#define FS 68                 // smem row stride (floats)
#define QTILE (128 * FS)      // Qhi/Qlo/Ps size
#define KVTILE (64 * FS)      // one K or V buffer

__global__ __launch_bounds__(256) void flash_attn_mma_kernel(
    const float* __restrict__ qkv, float* __restrict__ y)
{
    extern __shared__ float sm[];
    float* Qhi = sm;
    float* Qlo = Qhi + QTILE;
    float* Ksm = Qlo + QTILE;       // [2][64][FS]
    float* Vsm = Ksm + 2 * KVTILE;  // [2][64][FS]
    float* Psm = Vsm + 2 * KVTILE;  // [128][FS], per-warp-private 16-row slices

    const int qt = blockIdx.x;
    const int h  = blockIdx.y;
    const int b  = blockIdx.z;
    const int tid  = threadIdx.x;
    const int lane = tid & 31;
    const int warp = tid >> 5;
    const int g = lane >> 2;   // 0..7
    const int q = lane & 3;    // 0..3
    const int wm = warp * 16;

    const size_t rs = 3 * EQ;
    const size_t base = (size_t)b * TQ * rs;

    // ---- Load Q tile [128, 64], scale by 0.125, split hi/lo ----
    #pragma unroll
    for (int i = 0; i < 8; i++) {
        int idx = tid + i * 256;          // 0..2047
        int row = idx >> 4;               // 0..127
        int c4  = (idx & 15) * 4;         // 0..60
        const float* src = qkv + base + (size_t)(qt * 128 + row) * rs + h * DQ + c4;
        float4 v = *(const float4*)src;
        float vs[4] = {v.x * 0.125f, v.y * 0.125f, v.z * 0.125f, v.w * 0.125f};
        #pragma unroll
        for (int t = 0; t < 4; t++) {
            uint32_t hb = f2tf32(vs[t]);
            float hf = __uint_as_float(hb);
            uint32_t lb = f2tf32(vs[t] - hf);
            Qhi[row * FS + c4 + t] = hf;
            Qlo[row * FS + c4 + t] = __uint_as_float(lb);
        }
    }

    // ---- prologue: K/V tile 0 ----
    {
        #pragma unroll
        for (int i = 0; i < 4; i++) {
            int idx = tid + i * 256;       // 0..1023
            int row = idx >> 4;            // 0..63
            int c4  = (idx & 15) * 4;
            const float* kp = qkv + base + (size_t)row * rs + EQ + h * DQ + c4;
            cp16(smem_u32(&Ksm[row * FS + c4]), kp);
            cp16(smem_u32(&Vsm[row * FS + c4]), kp + EQ);
        }
        cp_commit();
    }

    float m0 = -1e30f, m1 = -1e30f, l0 = 0.f, l1 = 0.f;
    float o[8][4];
    #pragma unroll
    for (int n = 0; n < 8; n++)
        #pragma unroll
        for (int r = 0; r < 4; r++) o[n][r] = 0.f;

    const int jmax = 2 * qt + 1;

    for (int j = 0; j <= jmax; j++) {
        cp_wait<0>();
        __syncthreads();

        if (j < jmax) {
            const int nb = (j + 1) & 1;
            #pragma unroll
            for (int i = 0; i < 4; i++) {
                int idx = tid + i * 256;
                int row = idx >> 4;
                int c4  = (idx & 15) * 4;
                const float* kp = qkv + base + (size_t)((j + 1) * 64 + row) * rs + EQ + h * DQ + c4;
                cp16(smem_u32(&Ksm[nb * KVTILE + row * FS + c4]), kp);
                cp16(smem_u32(&Vsm[nb * KVTILE + row * FS + c4]), kp + EQ);
            }
            cp_commit();
        }

        const float* K = Ksm + (j & 1) * KVTILE;
        const float* V = Vsm + (j & 1) * KVTILE;

        // ---- S = Q K^T (split tf32) ----
        float s[8][4];
        #pragma unroll
        for (int n = 0; n < 8; n++)
            #pragma unroll
            for (int r = 0; r < 4; r++) s[n][r] = 0.f;

        #pragma unroll
        for (int ks = 0; ks < 8; ks++) {
            const int r0 = (wm + g) * FS, r1 = (wm + g + 8) * FS;
            const int c0 = ks * 8 + q, c1 = ks * 8 + q + 4;
            uint32_t ahi[4], alo[4];
            ahi[0] = __float_as_uint(Qhi[r0 + c0]);
            ahi[1] = __float_as_uint(Qhi[r1 + c0]);
            ahi[2] = __float_as_uint(Qhi[r0 + c1]);
            ahi[3] = __float_as_uint(Qhi[r1 + c1]);
            alo[0] = __float_as_uint(Qlo[r0 + c0]);
            alo[1] = __float_as_uint(Qlo[r1 + c0]);
            alo[2] = __float_as_uint(Qlo[r0 + c1]);
            alo[3] = __float_as_uint(Qlo[r1 + c1]);

            uint32_t bhi[8][2], blo[8][2];
            #pragma unroll
            for (int n = 0; n < 8; n++) {
                float k0 = K[(n * 8 + g) * FS + c0];
                float k1 = K[(n * 8 + g) * FS + c1];
                bhi[n][0] = f2tf32(k0);
                blo[n][0] = f2tf32(k0 - __uint_as_float(bhi[n][0]));
                bhi[n][1] = f2tf32(k1);
                blo[n][1] = f2tf32(k1 - __uint_as_float(bhi[n][1]));
            }
            #pragma unroll
            for (int n = 0; n < 8; n++) mma_tf32(s[n], ahi, bhi[n]);
            #pragma unroll
            for (int n = 0; n < 8; n++) mma_tf32(s[n], ahi, blo[n]);
            #pragma unroll
            for (int n = 0; n < 8; n++) mma_tf32(s[n], alo, bhi[n]);
        }

        // ---- causal mask (only last two kv tiles can intersect diagonal) ----
        if (j >= 2 * qt) {
            const int grow0 = qt * 128 + wm + g;
            const int grow1 = grow0 + 8;
            #pragma unroll
            for (int n = 0; n < 8; n++) {
                const int gc = j * 64 + n * 8 + 2 * q;
                if (gc     > grow0) s[n][0] = -1e30f;
                if (gc + 1 > grow0) s[n][1] = -1e30f;
                if (gc     > grow1) s[n][2] = -1e30f;
                if (gc + 1 > grow1) s[n][3] = -1e30f;
            }
        }

        // ---- online softmax (rows wm+g and wm+g+8) ----
        float mt0 = -1e30f, mt1 = -1e30f;
        #pragma unroll
        for (int n = 0; n < 8; n++) {
            mt0 = fmaxf(mt0, fmaxf(s[n][0], s[n][1]));
            mt1 = fmaxf(mt1, fmaxf(s[n][2], s[n][3]));
        }
        mt0 = fmaxf(mt0, __shfl_xor_sync(0xffffffffu, mt0, 1));
        mt0 = fmaxf(mt0, __shfl_xor_sync(0xffffffffu, mt0, 2));
        mt1 = fmaxf(mt1, __shfl_xor_sync(0xffffffffu, mt1, 1));
        mt1 = fmaxf(mt1, __shfl_xor_sync(0xffffffffu, mt1, 2));

        const float mn0 = fmaxf(m0, mt0);
        const float mn1 = fmaxf(m1, mt1);
        const float a0 = __expf(m0 - mn0);
        const float a1 = __expf(m1 - mn1);
        float rs0 = 0.f, rs1 = 0.f;

        float* prow0 = Psm + (wm + g) * FS;
        float* prow1 = Psm + (wm + g + 8) * FS;
        #pragma unroll
        for (int n = 0; n < 8; n++) {
            float p00 = __expf(s[n][0] - mn0);
            float p01 = __expf(s[n][1] - mn0);
            float p10 = __expf(s[n][2] - mn1);
            float p11 = __expf(s[n][3] - mn1);
            rs0 += p00 + p01;
            rs1 += p10 + p11;
            prow0[n * 8 + 2 * q]     = p00;
            prow0[n * 8 + 2 * q + 1] = p01;
            prow1[n * 8 + 2 * q]     = p10;
            prow1[n * 8 + 2 * q + 1] = p11;
            o[n][0] *= a0; o[n][1] *= a0;
            o[n][2] *= a1; o[n][3] *= a1;
        }
        rs0 += __shfl_xor_sync(0xffffffffu, rs0, 1);
        rs0 += __shfl_xor_sync(0xffffffffu, rs0, 2);
        rs1 += __shfl_xor_sync(0xffffffffu, rs1, 1);
        rs1 += __shfl_xor_sync(0xffffffffu, rs1, 2);
        l0 = l0 * a0 + rs0;
        l1 = l1 * a1 + rs1;
        m0 = mn0;
        m1 = mn1;
        __syncwarp();

        // ---- O += P V (plain tf32) ----
        #pragma unroll
        for (int ks = 0; ks < 8; ks++) {
            const int c0 = ks * 8 + q, c1 = ks * 8 + q + 4;
            uint32_t pa[4];
            pa[0] = f2tf32(Psm[(wm + g) * FS + c0]);
            pa[1] = f2tf32(Psm[(wm + g + 8) * FS + c0]);
            pa[2] = f2tf32(Psm[(wm + g) * FS + c1]);
            pa[3] = f2tf32(Psm[(wm + g + 8) * FS + c1]);
            uint32_t vb[8][2];
            #pragma unroll
            for (int n = 0; n < 8; n++) {
                vb[n][0] = f2tf32(V[c0 * FS + n * 8 + g]);
                vb[n][1] = f2tf32(V[c1 * FS + n * 8 + g]);
            }
            #pragma unroll
            for (int n = 0; n < 8; n++) mma_tf32(o[n], pa, vb[n]);
        }
    }

    // ---- epilogue ----
    const float inv0 = 1.f / l0;
    const float inv1 = 1.f / l1;
    const size_t row0 = (size_t)b * TQ + qt * 128 + wm + g;
    #pragma unroll
    for (int n = 0; n < 8; n++) {
        const int col = h * DQ + n * 8 + 2 * q;
        float2 v0 = make_float2(o[n][0] * inv0, o[n][1] * inv0);
        float2 v1 = make_float2(o[n][2] * inv1, o[n][3] * inv1);
        *(float2*)(g_y + row0 * EQ + col) = v0;
        *(float2*)(g_y + (row0 + 8) * EQ + col) = v1;
    }
    (void)y;
}

// ---------------------------------------------------------------------------
extern "C" void kernel_launch(void* const* d_in, const int* in_sizes, int n_in,
                              void* d_out, int out_size)
{
    const float* x     = (const float*)d_in[0];
    const float* Wqkv  = (const float*)d_in[1];
    const float* bqkv  = (const float*)d_in[2];
    const float* Wproj = (const float*)d_in[3];
    const float* bproj = (const float*)d_in[4];
    float* out = (float*)d_out;

    float* qkv = nullptr;
    float* y = nullptr;
    cudaGetSymbolAddress((void**)&qkv, g_qkv);
    cudaGetSymbolAddress((void**)&y, g_y);

    const int M = BQ * TQ;  // 8192

    // 1) QKV GEMM (tf32 tensor cores)
    {
        dim3 grid(3 * EQ / 128, M / 128);
        gemm_tf32_bias_kernel<<<grid, 256>>>(x, Wqkv, bqkv, qkv, M, 3 * EQ, EQ);
    }

    // 2) Flash attention (tf32 MMA) -> g_y
    {
        const int smem_bytes = (3 * QTILE + 4 * KVTILE) * (int)sizeof(float);  // 174080
        cudaFuncSetAttribute(flash_attn_mma_kernel,
                             cudaFuncAttributeMaxDynamicSharedMemorySize, smem_bytes);
        dim3 grid(TQ / 128, HQ, BQ);
        flash_attn_mma_kernel<<<grid, 256, smem_bytes>>>(qkv, y);
    }

    // 3) Proj GEMM (tf32 tensor cores) -> d_out
    {
        dim3 grid(EQ / 128, M / 128);
        gemm_tf32_bias_kernel<<<grid, 256>>>(y, Wproj, bproj, out, M, EQ, EQ);
    }

    (void)in_sizes; (void)n_in; (void)out_size;
}

// round 9
// speedup vs baseline: 2.7278x; 1.0835x over previous
#include <cuda_runtime.h>
#include <math.h>
#include <stdint.h>

#define BQ 4
#define TQ 2048
#define EQ 1024
#define HQ 16
#define DQ 64

// Scratch (allocation-free rule: __device__ globals)
__device__ float g_qkv[(size_t)BQ * TQ * 3 * EQ];   // [8192, 3072] fp32
__device__ float g_y[(size_t)BQ * TQ * EQ];         // [8192, 1024] tf32 bits
__device__ float g_xtf[(size_t)BQ * TQ * EQ];       // x in tf32 bits
__device__ float g_wqkv_tf[(size_t)EQ * 3 * EQ];    // W_qkv tf32 bits
__device__ float g_wproj_tf[(size_t)EQ * EQ];       // W_proj tf32 bits
__device__ float g_khi[(size_t)BQ * TQ * EQ];       // K hi tf32 bits, dense [B*T, E]
__device__ float g_klo[(size_t)BQ * TQ * EQ];       // K lo tf32 bits
__device__ float g_vtf[(size_t)BQ * TQ * EQ];       // V tf32 bits

// ---------------------------------------------------------------------------
// helpers
// ---------------------------------------------------------------------------
__device__ __forceinline__ uint32_t smem_u32(const void* p) {
    return (uint32_t)__cvta_generic_to_shared(p);
}

__device__ __forceinline__ void cp16(uint32_t dst, const void* src) {
    asm volatile("cp.async.cg.shared.global [%0], [%1], 16;\n" ::"r"(dst), "l"(src));
}

__device__ __forceinline__ void cp_commit() {
    asm volatile("cp.async.commit_group;\n");
}

template <int N>
__device__ __forceinline__ void cp_wait() {
    asm volatile("cp.async.wait_group %0;\n" ::"n"(N));
}

__device__ __forceinline__ uint32_t f2tf32(float f) {
    uint32_t u;
    asm("cvt.rna.tf32.f32 %0, %1;\n" : "=r"(u) : "f"(f));
    return u;
}

__device__ __forceinline__ float tf32f(float f) {
    return __uint_as_float(f2tf32(f));
}

__device__ __forceinline__ void mma_tf32(float* c, const uint32_t* a, const uint32_t* b) {
    asm volatile(
        "mma.sync.aligned.m16n8k8.row.col.f32.tf32.tf32.f32 "
        "{%0,%1,%2,%3},{%4,%5,%6,%7},{%8,%9},{%0,%1,%2,%3};\n"
        : "+f"(c[0]), "+f"(c[1]), "+f"(c[2]), "+f"(c[3])
        : "r"(a[0]), "r"(a[1]), "r"(a[2]), "r"(a[3]), "r"(b[0]), "r"(b[1]));
}

// ---------------------------------------------------------------------------
// Prepass: elementwise tf32 conversion (fp32 -> tf32 bits stored as fp32)
// ---------------------------------------------------------------------------
__global__ __launch_bounds__(256) void cvt_tf32_kernel(
    const float4* __restrict__ src, float4* __restrict__ dst, int n4)
{
    int i = blockIdx.x * 256 + threadIdx.x;
    int stride = gridDim.x * 256;
    for (; i < n4; i += stride) {
        float4 v = src[i];
        v.x = tf32f(v.x); v.y = tf32f(v.y); v.z = tf32f(v.z); v.w = tf32f(v.w);
        dst[i] = v;
    }
}

// ---------------------------------------------------------------------------
// Prepass: split K into (hi, lo) tf32 pair and convert V to tf32.
// qkv layout [B*T, 3E]; outputs dense [B*T, E].
// ---------------------------------------------------------------------------
__global__ __launch_bounds__(256) void split_kv_kernel(const float* __restrict__ qkv)
{
    // one float4 per thread iteration over B*T*E/4 quads
    const int n4 = BQ * TQ * EQ / 4;
    int i = blockIdx.x * 256 + threadIdx.x;
    int stride = gridDim.x * 256;
    for (; i < n4; i += stride) {
        int row = i / (EQ / 4);
        int c4 = (i % (EQ / 4)) * 4;
        const float* kp = qkv + (size_t)row * (3 * EQ) + EQ + c4;
        float4 k = *(const float4*)kp;
        float4 v = *(const float4*)(kp + EQ);
        float4 hi, lo;
        hi.x = tf32f(k.x); lo.x = tf32f(k.x - hi.x);
        hi.y = tf32f(k.y); lo.y = tf32f(k.y - hi.y);
        hi.z = tf32f(k.z); lo.z = tf32f(k.z - hi.z);
        hi.w = tf32f(k.w); lo.w = tf32f(k.w - hi.w);
        v.x = tf32f(v.x); v.y = tf32f(v.y); v.z = tf32f(v.z); v.w = tf32f(v.w);
        size_t o = (size_t)row * EQ + c4;
        *(float4*)(g_khi + o) = hi;
        *(float4*)(g_klo + o) = lo;
        *(float4*)(g_vtf + o) = v;
    }
}

// ---------------------------------------------------------------------------
// tf32 tensor-core GEMM + bias. A and W are PRE-CONVERTED tf32 bits.
// 128x128 block tile, TILE_K=16, 256 threads. cp.async double-buffered.
// ---------------------------------------------------------------------------
#define GK 16
#define ASTRIDE 20
#define BSTRIDE 136

__global__ __launch_bounds__(256) void gemm_tf32_bias_kernel(
    const float* __restrict__ A, const float* __restrict__ W,
    const float* __restrict__ bias, float* __restrict__ C,
    int M, int N, int K)
{
    __shared__ float As[2][128][ASTRIDE];
    __shared__ float Bs[2][GK][BSTRIDE];

    const int tid  = threadIdx.x;
    const int lane = tid & 31;
    const int warp = tid >> 5;
    const int wm   = (warp >> 1) * 32;
    const int wn   = (warp & 1) * 64;
    const int g    = lane >> 2;
    const int q    = lane & 3;

    const int bm = blockIdx.y * 128;
    const int bn = blockIdx.x * 128;

    float acc[2][8][4];
    #pragma unroll
    for (int i = 0; i < 2; i++)
        #pragma unroll
        for (int j = 0; j < 8; j++)
            #pragma unroll
            for (int r = 0; r < 4; r++) acc[i][j][r] = 0.f;

    const int nt = K / GK;

    {
        #pragma unroll
        for (int i = 0; i < 2; i++) {
            int j = tid + i * 256;
            int row = j >> 2, c4 = (j & 3) * 4;
            cp16(smem_u32(&As[0][row][c4]), A + (size_t)(bm + row) * K + c4);
        }
        #pragma unroll
        for (int i = 0; i < 2; i++) {
            int j = tid + i * 256;
            int kr = j >> 5, nc = (j & 31) * 4;
            cp16(smem_u32(&Bs[0][kr][nc]), W + (size_t)kr * N + bn + nc);
        }
        cp_commit();
    }

    for (int kt = 0; kt < nt; kt++) {
        const int buf = kt & 1;
        if (kt + 1 < nt) {
            const int nb = buf ^ 1;
            const int k0 = (kt + 1) * GK;
            #pragma unroll
            for (int i = 0; i < 2; i++) {
                int j = tid + i * 256;
                int row = j >> 2, c4 = (j & 3) * 4;
                cp16(smem_u32(&As[nb][row][c4]), A + (size_t)(bm + row) * K + k0 + c4);
            }
            #pragma unroll
            for (int i = 0; i < 2; i++) {
                int j = tid + i * 256;
                int kr = j >> 5, nc = (j & 31) * 4;
                cp16(smem_u32(&Bs[nb][kr][nc]), W + (size_t)(k0 + kr) * N + bn + nc);
            }
            cp_commit();
            cp_wait<1>();
        } else {
            cp_wait<0>();
        }
        __syncthreads();

        #pragma unroll
        for (int ks = 0; ks < GK; ks += 8) {
            uint32_t afr[2][4];
            #pragma unroll
            for (int i = 0; i < 2; i++) {
                int r0 = wm + i * 16 + g;
                afr[i][0] = __float_as_uint(As[buf][r0][ks + q]);
                afr[i][1] = __float_as_uint(As[buf][r0 + 8][ks + q]);
                afr[i][2] = __float_as_uint(As[buf][r0][ks + q + 4]);
                afr[i][3] = __float_as_uint(As[buf][r0 + 8][ks + q + 4]);
            }
            uint32_t bfr[8][2];
            #pragma unroll
            for (int j = 0; j < 8; j++) {
                int n0 = wn + j * 8 + g;
                bfr[j][0] = __float_as_uint(Bs[buf][ks + q][n0]);
                bfr[j][1] = __float_as_uint(Bs[buf][ks + q + 4][n0]);
            }
            #pragma unroll
            for (int i = 0; i < 2; i++)
                #pragma unroll
                for (int j = 0; j < 8; j++)
                    mma_tf32(acc[i][j], afr[i], bfr[j]);
        }
        __syncthreads();
    }

    #pragma unroll
    for (int i = 0; i < 2; i++) {
        #pragma unroll
        for (int j = 0; j < 8; j++) {
            int row = bm + wm + i * 16 + g;
            int col = bn + wn + j * 8 + 2 * q;
            float bx = bias[col], by = bias[col + 1];
            float2 v0 = make_float2(acc[i][j][0] + bx, acc[i][j][1] + by);
            float2 v1 = make_float2(acc[i][j][2] + bx, acc[i][j][3] + by);
            *(float2*)(C + (size_t)row * N + col) = v0;
            *(float2*)(C + (size_t)(row + 8) * N + col) = v1;
        }
    }
}

// ---------------------------------------------------------------------------
// Flash attention (causal), tf32 MMA. K/V pre-split+converted in global.
// Block: 128 q-rows, 8 warps (m16 each). KV tiles 64 rows, double-buffered.
// Inner loops contain no CVT: pure LDS + MMA.
// ---------------------------------------------------------------------------
#define FS 68
#define QTILE (128 * FS)
#define KVTILE (64 * FS)

__global__ __launch_bounds__(256) void flash_attn_mma_kernel(
    const float* __restrict__ qkv)
{
    extern __shared__ float sm[];
    float* Qhi = sm;
    float* Qlo = Qhi + QTILE;
    float* Khs = Qlo + QTILE;        // [2][64][FS] K hi
    float* Kls = Khs + 2 * KVTILE;   // [2][64][FS] K lo
    float* Vsm = Kls + 2 * KVTILE;   // [2][64][FS] V (tf32)
    float* Psm = Vsm + 2 * KVTILE;   // [128][FS] P (tf32 bits), warp-private rows

    const int qt = blockIdx.x;
    const int h  = blockIdx.y;
    const int b  = blockIdx.z;
    const int tid  = threadIdx.x;
    const int lane = tid & 31;
    const int warp = tid >> 5;
    const int g = lane >> 2;
    const int q = lane & 3;
    const int wm = warp * 16;

    const size_t rs = 3 * EQ;
    const size_t baseq = (size_t)b * TQ * rs;           // qkv (Q part)
    const size_t basekv = (size_t)b * TQ * EQ + h * DQ; // dense K/V arrays

    // ---- Load Q tile [128, 64], scale, split hi/lo ----
    #pragma unroll
    for (int i = 0; i < 8; i++) {
        int idx = tid + i * 256;
        int row = idx >> 4;
        int c4  = (idx & 15) * 4;
        const float* src = qkv + baseq + (size_t)(qt * 128 + row) * rs + h * DQ + c4;
        float4 v = *(const float4*)src;
        float vs[4] = {v.x * 0.125f, v.y * 0.125f, v.z * 0.125f, v.w * 0.125f};
        #pragma unroll
        for (int t = 0; t < 4; t++) {
            float hf = tf32f(vs[t]);
            Qhi[row * FS + c4 + t] = hf;
            Qlo[row * FS + c4 + t] = tf32f(vs[t] - hf);
        }
    }

    // ---- prologue: K/V tile 0 ----
    {
        #pragma unroll
        for (int i = 0; i < 4; i++) {
            int idx = tid + i * 256;
            int row = idx >> 4;
            int c4  = (idx & 15) * 4;
            size_t go = basekv + (size_t)row * EQ + c4;
            cp16(smem_u32(&Khs[row * FS + c4]), g_khi + go);
            cp16(smem_u32(&Kls[row * FS + c4]), g_klo + go);
            cp16(smem_u32(&Vsm[row * FS + c4]), g_vtf + go);
        }
        cp_commit();
    }

    float m0 = -1e30f, m1 = -1e30f, l0 = 0.f, l1 = 0.f;
    float o[8][4];
    #pragma unroll
    for (int n = 0; n < 8; n++)
        #pragma unroll
        for (int r = 0; r < 4; r++) o[n][r] = 0.f;

    const int jmax = 2 * qt + 1;

    for (int j = 0; j <= jmax; j++) {
        cp_wait<0>();
        __syncthreads();

        if (j < jmax) {
            const int nb = (j + 1) & 1;
            #pragma unroll
            for (int i = 0; i < 4; i++) {
                int idx = tid + i * 256;
                int row = idx >> 4;
                int c4  = (idx & 15) * 4;
                size_t go = basekv + (size_t)((j + 1) * 64 + row) * EQ + c4;
                cp16(smem_u32(&Khs[nb * KVTILE + row * FS + c4]), g_khi + go);
                cp16(smem_u32(&Kls[nb * KVTILE + row * FS + c4]), g_klo + go);
                cp16(smem_u32(&Vsm[nb * KVTILE + row * FS + c4]), g_vtf + go);
            }
            cp_commit();
        }

        const float* Kh = Khs + (j & 1) * KVTILE;
        const float* Kl = Kls + (j & 1) * KVTILE;
        const float* V  = Vsm + (j & 1) * KVTILE;

        // ---- S = Q K^T (split tf32, 3 MMAs) ----
        float s[8][4];
        #pragma unroll
        for (int n = 0; n < 8; n++)
            #pragma unroll
            for (int r = 0; r < 4; r++) s[n][r] = 0.f;

        #pragma unroll
        for (int ks = 0; ks < 8; ks++) {
            const int r0 = (wm + g) * FS, r1 = (wm + g + 8) * FS;
            const int c0 = ks * 8 + q, c1 = ks * 8 + q + 4;
            uint32_t ahi[4], alo[4];
            ahi[0] = __float_as_uint(Qhi[r0 + c0]);
            ahi[1] = __float_as_uint(Qhi[r1 + c0]);
            ahi[2] = __float_as_uint(Qhi[r0 + c1]);
            ahi[3] = __float_as_uint(Qhi[r1 + c1]);
            alo[0] = __float_as_uint(Qlo[r0 + c0]);
            alo[1] = __float_as_uint(Qlo[r1 + c0]);
            alo[2] = __float_as_uint(Qlo[r0 + c1]);
            alo[3] = __float_as_uint(Qlo[r1 + c1]);

            uint32_t bhi[8][2], blo[8][2];
            #pragma unroll
            for (int n = 0; n < 8; n++) {
                const int kr = (n * 8 + g) * FS;
                bhi[n][0] = __float_as_uint(Kh[kr + c0]);
                bhi[n][1] = __float_as_uint(Kh[kr + c1]);
                blo[n][0] = __float_as_uint(Kl[kr + c0]);
                blo[n][1] = __float_as_uint(Kl[kr + c1]);
            }
            #pragma unroll
            for (int n = 0; n < 8; n++) mma_tf32(s[n], ahi, bhi[n]);
            #pragma unroll
            for (int n = 0; n < 8; n++) mma_tf32(s[n], ahi, blo[n]);
            #pragma unroll
            for (int n = 0; n < 8; n++) mma_tf32(s[n], alo, bhi[n]);
        }

        // ---- causal mask ----
        if (j >= 2 * qt) {
            const int grow0 = qt * 128 + wm + g;
            const int grow1 = grow0 + 8;
            #pragma unroll
            for (int n = 0; n < 8; n++) {
                const int gc = j * 64 + n * 8 + 2 * q;
                if (gc     > grow0) s[n][0] = -1e30f;
                if (gc + 1 > grow0) s[n][1] = -1e30f;
                if (gc     > grow1) s[n][2] = -1e30f;
                if (gc + 1 > grow1) s[n][3] = -1e30f;
            }
        }

        // ---- online softmax ----
        float mt0 = -1e30f, mt1 = -1e30f;
        #pragma unroll
        for (int n = 0; n < 8; n++) {
            mt0 = fmaxf(mt0, fmaxf(s[n][0], s[n][1]));
            mt1 = fmaxf(mt1, fmaxf(s[n][2], s[n][3]));
        }
        mt0 = fmaxf(mt0, __shfl_xor_sync(0xffffffffu, mt0, 1));
        mt0 = fmaxf(mt0, __shfl_xor_sync(0xffffffffu, mt0, 2));
        mt1 = fmaxf(mt1, __shfl_xor_sync(0xffffffffu, mt1, 1));
        mt1 = fmaxf(mt1, __shfl_xor_sync(0xffffffffu, mt1, 2));

        const float mn0 = fmaxf(m0, mt0);
        const float mn1 = fmaxf(m1, mt1);
        const float a0 = __expf(m0 - mn0);
        const float a1 = __expf(m1 - mn1);
        float rs0 = 0.f, rs1 = 0.f;

        float* prow0 = Psm + (wm + g) * FS;
        float* prow1 = Psm + (wm + g + 8) * FS;
        #pragma unroll
        for (int n = 0; n < 8; n++) {
            float p00 = __expf(s[n][0] - mn0);
            float p01 = __expf(s[n][1] - mn0);
            float p10 = __expf(s[n][2] - mn1);
            float p11 = __expf(s[n][3] - mn1);
            rs0 += p00 + p01;
            rs1 += p10 + p11;
            prow0[n * 8 + 2 * q]     = tf32f(p00);
            prow0[n * 8 + 2 * q + 1] = tf32f(p01);
            prow1[n * 8 + 2 * q]     = tf32f(p10);
            prow1[n * 8 + 2 * q + 1] = tf32f(p11);
            o[n][0] *= a0; o[n][1] *= a0;
            o[n][2] *= a1; o[n][3] *= a1;
        }
        rs0 += __shfl_xor_sync(0xffffffffu, rs0, 1);
        rs0 += __shfl_xor_sync(0xffffffffu, rs0, 2);
        rs1 += __shfl_xor_sync(0xffffffffu, rs1, 1);
        rs1 += __shfl_xor_sync(0xffffffffu, rs1, 2);
        l0 = l0 * a0 + rs0;
        l1 = l1 * a1 + rs1;
        m0 = mn0;
        m1 = mn1;
        __syncwarp();

        // ---- O += P V (no CVT: P and V already tf32 bits) ----
        #pragma unroll
        for (int ks = 0; ks < 8; ks++) {
            const int c0 = ks * 8 + q, c1 = ks * 8 + q + 4;
            uint32_t pa[4];
            pa[0] = __float_as_uint(Psm[(wm + g) * FS + c0]);
            pa[1] = __float_as_uint(Psm[(wm + g + 8) * FS + c0]);
            pa[2] = __float_as_uint(Psm[(wm + g) * FS + c1]);
            pa[3] = __float_as_uint(Psm[(wm + g + 8) * FS + c1]);
            uint32_t vb[8][2];
            #pragma unroll
            for (int n = 0; n < 8; n++) {
                vb[n][0] = __float_as_uint(V[c0 * FS + n * 8 + g]);
                vb[n][1] = __float_as_uint(V[c1 * FS + n * 8 + g]);
            }
            #pragma unroll
            for (int n = 0; n < 8; n++) mma_tf32(o[n], pa, vb[n]);
        }
    }

    // ---- epilogue: write y pre-converted to tf32 bits ----
    const float inv0 = 1.f / l0;
    const float inv1 = 1.f / l1;
    const size_t row0 = (size_t)b * TQ + qt * 128 + wm + g;
    #pragma unroll
    for (int n = 0; n < 8; n++) {
        const int col = h * DQ + n * 8 + 2 * q;
        float2 v0 = make_float2(tf32f(o[n][0] * inv0), tf32f(o[n][1] * inv0));
        float2 v1 = make_float2(tf32f(o[n][2] * inv1), tf32f(o[n][3] * inv1));
        *(float2*)(g_y + row0 * EQ + col) = v0;
        *(float2*)(g_y + (row0 + 8) * EQ + col) = v1;
    }
}

// ---------------------------------------------------------------------------
extern "C" void kernel_launch(void* const* d_in, const int* in_sizes, int n_in,
                              void* d_out, int out_size)
{
    const float* x     = (const float*)d_in[0];
    const float* Wqkv  = (const float*)d_in[1];
    const float* bqkv  = (const float*)d_in[2];
    const float* Wproj = (const float*)d_in[3];
    const float* bproj = (const float*)d_in[4];
    float* out = (float*)d_out;

    float *qkv, *y, *xtf, *wqkv_tf, *wproj_tf;
    cudaGetSymbolAddress((void**)&qkv, g_qkv);
    cudaGetSymbolAddress((void**)&y, g_y);
    cudaGetSymbolAddress((void**)&xtf, g_xtf);
    cudaGetSymbolAddress((void**)&wqkv_tf, g_wqkv_tf);
    cudaGetSymbolAddress((void**)&wproj_tf, g_wproj_tf);

    const int M = BQ * TQ;  // 8192

    // 0) tf32 prepasses for GEMM operands
    cvt_tf32_kernel<<<592, 256>>>((const float4*)x, (float4*)xtf, M * EQ / 4);
    cvt_tf32_kernel<<<592, 256>>>((const float4*)Wqkv, (float4*)wqkv_tf, EQ * 3 * EQ / 4);
    cvt_tf32_kernel<<<592, 256>>>((const float4*)Wproj, (float4*)wproj_tf, EQ * EQ / 4);

    // 1) QKV GEMM (tf32 tensor cores)
    {
        dim3 grid(3 * EQ / 128, M / 128);
        gemm_tf32_bias_kernel<<<grid, 256>>>(xtf, wqkv_tf, bqkv, qkv, M, 3 * EQ, EQ);
    }

    // 1.5) split K -> (hi, lo), convert V
    split_kv_kernel<<<592, 256>>>(qkv);

    // 2) Flash attention (tf32 MMA) -> g_y (tf32 bits)
    {
        const int smem_bytes = (3 * QTILE + 6 * KVTILE) * (int)sizeof(float);  // 208896
        cudaFuncSetAttribute(flash_attn_mma_kernel,
                             cudaFuncAttributeMaxDynamicSharedMemorySize, smem_bytes);
        dim3 grid(TQ / 128, HQ, BQ);
        flash_attn_mma_kernel<<<grid, 256, smem_bytes>>>(qkv);
    }

    // 3) Proj GEMM (tf32 tensor cores) -> d_out
    {
        dim3 grid(EQ / 128, M / 128);
        gemm_tf32_bias_kernel<<<grid, 256>>>(y, wproj_tf, bproj, out, M, EQ, EQ);
    }

    (void)in_sizes; (void)n_in; (void)out_size;
}

// round 12
// speedup vs baseline: 3.0577x; 1.1209x over previous
#include <cuda_runtime.h>
#include <cuda_bf16.h>
#include <math.h>
#include <stdint.h>

#define BQ 4
#define TQ 2048
#define EQ 1024
#define HQ 16
#define DQ 64

// Scratch (allocation-free rule: __device__ globals)
__device__ float g_qkv[(size_t)BQ * TQ * 3 * EQ];   // [8192, 3072] fp32
__device__ float g_y[(size_t)BQ * TQ * EQ];         // [8192, 1024] tf32 bits
__device__ float g_xtf[(size_t)BQ * TQ * EQ];       // x in tf32 bits
__device__ float g_wqkv_tf[(size_t)EQ * 3 * EQ];    // W_qkv tf32 bits
__device__ float g_wproj_tf[(size_t)EQ * EQ];       // W_proj tf32 bits
__device__ __nv_bfloat16 g_khi16[(size_t)BQ * TQ * EQ];  // K hi bf16, dense [B*T, E]
__device__ __nv_bfloat16 g_klo16[(size_t)BQ * TQ * EQ];  // K lo bf16
__device__ float g_vtf[(size_t)BQ * TQ * EQ];            // V tf32 bits

// ---------------------------------------------------------------------------
// helpers
// ---------------------------------------------------------------------------
__device__ __forceinline__ uint32_t smem_u32(const void* p) {
    return (uint32_t)__cvta_generic_to_shared(p);
}

__device__ __forceinline__ void cp16(uint32_t dst, const void* src) {
    asm volatile("cp.async.cg.shared.global [%0], [%1], 16;\n" ::"r"(dst), "l"(src));
}

__device__ __forceinline__ void cp_commit() {
    asm volatile("cp.async.commit_group;\n");
}

template <int N>
__device__ __forceinline__ void cp_wait() {
    asm volatile("cp.async.wait_group %0;\n" ::"n"(N));
}

__device__ __forceinline__ uint32_t f2tf32(float f) {
    uint32_t u;
    asm("cvt.rna.tf32.f32 %0, %1;\n" : "=r"(u) : "f"(f));
    return u;
}

__device__ __forceinline__ float tf32f(float f) {
    return __uint_as_float(f2tf32(f));
}

__device__ __forceinline__ void mma_tf32(float* c, const uint32_t* a, const uint32_t* b) {
    asm volatile(
        "mma.sync.aligned.m16n8k8.row.col.f32.tf32.tf32.f32 "
        "{%0,%1,%2,%3},{%4,%5,%6,%7},{%8,%9},{%0,%1,%2,%3};\n"
        : "+f"(c[0]), "+f"(c[1]), "+f"(c[2]), "+f"(c[3])
        : "r"(a[0]), "r"(a[1]), "r"(a[2]), "r"(a[3]), "r"(b[0]), "r"(b[1]));
}

__device__ __forceinline__ void mma_bf16(float* c, const uint32_t* a, const uint32_t* b) {
    asm volatile(
        "mma.sync.aligned.m16n8k16.row.col.f32.bf16.bf16.f32 "
        "{%0,%1,%2,%3},{%4,%5,%6,%7},{%8,%9},{%0,%1,%2,%3};\n"
        : "+f"(c[0]), "+f"(c[1]), "+f"(c[2]), "+f"(c[3])
        : "r"(a[0]), "r"(a[1]), "r"(a[2]), "r"(a[3]), "r"(b[0]), "r"(b[1]));
}

// ---------------------------------------------------------------------------
// Prepass: elementwise tf32 conversion (fp32 -> tf32 bits stored as fp32)
// ---------------------------------------------------------------------------
__global__ __launch_bounds__(256) void cvt_tf32_kernel(
    const float4* __restrict__ src, float4* __restrict__ dst, int n4)
{
    int i = blockIdx.x * 256 + threadIdx.x;
    int stride = gridDim.x * 256;
    for (; i < n4; i += stride) {
        float4 v = src[i];
        v.x = tf32f(v.x); v.y = tf32f(v.y); v.z = tf32f(v.z); v.w = tf32f(v.w);
        dst[i] = v;
    }
}

// ---------------------------------------------------------------------------
// Prepass: K -> (hi, lo) bf16 planes; V -> tf32. qkv layout [B*T, 3E].
// ---------------------------------------------------------------------------
__global__ __launch_bounds__(256) void split_kv_kernel(const float* __restrict__ qkv)
{
    const int n4 = BQ * TQ * EQ / 4;
    int i = blockIdx.x * 256 + threadIdx.x;
    int stride = gridDim.x * 256;
    for (; i < n4; i += stride) {
        int row = i / (EQ / 4);
        int c4 = (i % (EQ / 4)) * 4;
        const float* kp = qkv + (size_t)row * (3 * EQ) + EQ + c4;
        float4 k = *(const float4*)kp;
        float4 v = *(const float4*)(kp + EQ);

        __nv_bfloat16 hx = __float2bfloat16_rn(k.x);
        __nv_bfloat16 hy = __float2bfloat16_rn(k.y);
        __nv_bfloat16 hz = __float2bfloat16_rn(k.z);
        __nv_bfloat16 hw = __float2bfloat16_rn(k.w);
        __nv_bfloat16 lx = __float2bfloat16_rn(k.x - __bfloat162float(hx));
        __nv_bfloat16 ly = __float2bfloat16_rn(k.y - __bfloat162float(hy));
        __nv_bfloat16 lz = __float2bfloat16_rn(k.z - __bfloat162float(hz));
        __nv_bfloat16 lw = __float2bfloat16_rn(k.w - __bfloat162float(hw));

        size_t o = (size_t)row * EQ + c4;
        *(__nv_bfloat162*)(g_khi16 + o)     = __nv_bfloat162(hx, hy);
        *(__nv_bfloat162*)(g_khi16 + o + 2) = __nv_bfloat162(hz, hw);
        *(__nv_bfloat162*)(g_klo16 + o)     = __nv_bfloat162(lx, ly);
        *(__nv_bfloat162*)(g_klo16 + o + 2) = __nv_bfloat162(lz, lw);

        v.x = tf32f(v.x); v.y = tf32f(v.y); v.z = tf32f(v.z); v.w = tf32f(v.w);
        *(float4*)(g_vtf + o) = v;
    }
}

// ---------------------------------------------------------------------------
// tf32 tensor-core GEMM + bias (operands pre-converted tf32 bits).
// ---------------------------------------------------------------------------
#define GK 16
#define ASTRIDE 20
#define BSTRIDE 136

__global__ __launch_bounds__(256) void gemm_tf32_bias_kernel(
    const float* __restrict__ A, const float* __restrict__ W,
    const float* __restrict__ bias, float* __restrict__ C,
    int M, int N, int K)
{
    __shared__ float As[2][128][ASTRIDE];
    __shared__ float Bs[2][GK][BSTRIDE];

    const int tid  = threadIdx.x;
    const int lane = tid & 31;
    const int warp = tid >> 5;
    const int wm   = (warp >> 1) * 32;
    const int wn   = (warp & 1) * 64;
    const int g    = lane >> 2;
    const int q    = lane & 3;

    const int bm = blockIdx.y * 128;
    const int bn = blockIdx.x * 128;

    float acc[2][8][4];
    #pragma unroll
    for (int i = 0; i < 2; i++)
        #pragma unroll
        for (int j = 0; j < 8; j++)
            #pragma unroll
            for (int r = 0; r < 4; r++) acc[i][j][r] = 0.f;

    const int nt = K / GK;

    {
        #pragma unroll
        for (int i = 0; i < 2; i++) {
            int j = tid + i * 256;
            int row = j >> 2, c4 = (j & 3) * 4;
            cp16(smem_u32(&As[0][row][c4]), A + (size_t)(bm + row) * K + c4);
        }
        #pragma unroll
        for (int i = 0; i < 2; i++) {
            int j = tid + i * 256;
            int kr = j >> 5, nc = (j & 31) * 4;
            cp16(smem_u32(&Bs[0][kr][nc]), W + (size_t)kr * N + bn + nc);
        }
        cp_commit();
    }

    for (int kt = 0; kt < nt; kt++) {
        const int buf = kt & 1;
        if (kt + 1 < nt) {
            const int nb = buf ^ 1;
            const int k0 = (kt + 1) * GK;
            #pragma unroll
            for (int i = 0; i < 2; i++) {
                int j = tid + i * 256;
                int row = j >> 2, c4 = (j & 3) * 4;
                cp16(smem_u32(&As[nb][row][c4]), A + (size_t)(bm + row) * K + k0 + c4);
            }
            #pragma unroll
            for (int i = 0; i < 2; i++) {
                int j = tid + i * 256;
                int kr = j >> 5, nc = (j & 31) * 4;
                cp16(smem_u32(&Bs[nb][kr][nc]), W + (size_t)(k0 + kr) * N + bn + nc);
            }
            cp_commit();
            cp_wait<1>();
        } else {
            cp_wait<0>();
        }
        __syncthreads();

        #pragma unroll
        for (int ks = 0; ks < GK; ks += 8) {
            uint32_t afr[2][4];
            #pragma unroll
            for (int i = 0; i < 2; i++) {
                int r0 = wm + i * 16 + g;
                afr[i][0] = __float_as_uint(As[buf][r0][ks + q]);
                afr[i][1] = __float_as_uint(As[buf][r0 + 8][ks + q]);
                afr[i][2] = __float_as_uint(As[buf][r0][ks + q + 4]);
                afr[i][3] = __float_as_uint(As[buf][r0 + 8][ks + q + 4]);
            }
            uint32_t bfr[8][2];
            #pragma unroll
            for (int j = 0; j < 8; j++) {
                int n0 = wn + j * 8 + g;
                bfr[j][0] = __float_as_uint(Bs[buf][ks + q][n0]);
                bfr[j][1] = __float_as_uint(Bs[buf][ks + q + 4][n0]);
            }
            #pragma unroll
            for (int i = 0; i < 2; i++)
                #pragma unroll
                for (int j = 0; j < 8; j++)
                    mma_tf32(acc[i][j], afr[i], bfr[j]);
        }
        __syncthreads();
    }

    #pragma unroll
    for (int i = 0; i < 2; i++) {
        #pragma unroll
        for (int j = 0; j < 8; j++) {
            int row = bm + wm + i * 16 + g;
            int col = bn + wn + j * 8 + 2 * q;
            float bx = bias[col], by = bias[col + 1];
            float2 v0 = make_float2(acc[i][j][0] + bx, acc[i][j][1] + by);
            float2 v1 = make_float2(acc[i][j][2] + bx, acc[i][j][3] + by);
            *(float2*)(C + (size_t)row * N + col) = v0;
            *(float2*)(C + (size_t)(row + 8) * N + col) = v1;
        }
    }
}

// ---------------------------------------------------------------------------
// Flash attention (causal).
// S = Q K^T via split-bf16 m16n8k16 (3 MMAs per k16): Qhi*Khi + Qhi*Klo + Qlo*Khi.
// PV via plain tf32 m16n8k8. K hi/lo bf16 planes and V tf32 pre-built in global.
// Block: 128 q-rows, 8 warps (m16 each). KV tiles 64 rows, double-buffered.
// ---------------------------------------------------------------------------
#define ST 72                  // bf16 smem row stride (elements)
#define FS 68                  // fp32 smem row stride (floats)
#define QP (128 * ST)          // one Q bf16 plane (elements)
#define KP (64 * ST)           // one K bf16 plane per buffer (elements)
#define VT (64 * FS)           // one V fp32 buffer (floats)

__global__ __launch_bounds__(256) void flash_attn_mma_kernel(
    const float* __restrict__ qkv)
{
    extern __shared__ char smraw[];
    __nv_bfloat16* Qhi = (__nv_bfloat16*)smraw;      // [128][ST]
    __nv_bfloat16* Qlo = Qhi + QP;                   // [128][ST]
    __nv_bfloat16* Khs = Qlo + QP;                   // [2][64][ST]
    __nv_bfloat16* Kls = Khs + 2 * KP;               // [2][64][ST]
    float* Vsm = (float*)(Kls + 2 * KP);             // [2][64][FS]
    float* Psm = Vsm + 2 * VT;                       // [128][FS]

    const int qt = blockIdx.x;
    const int h  = blockIdx.y;
    const int b  = blockIdx.z;
    const int tid  = threadIdx.x;
    const int lane = tid & 31;
    const int warp = tid >> 5;
    const int g = lane >> 2;
    const int q = lane & 3;
    const int wm = warp * 16;

    const size_t rs = 3 * EQ;
    const size_t baseq = (size_t)b * TQ * rs;
    const size_t basekv = (size_t)b * TQ * EQ + h * DQ;

    // ---- Load Q tile [128, 64], scale, split to bf16 hi/lo planes ----
    #pragma unroll
    for (int i = 0; i < 8; i++) {
        int idx = tid + i * 256;
        int row = idx >> 4;
        int c4  = (idx & 15) * 4;
        const float* src = qkv + baseq + (size_t)(qt * 128 + row) * rs + h * DQ + c4;
        float4 v = *(const float4*)src;
        float vs[4] = {v.x * 0.125f, v.y * 0.125f, v.z * 0.125f, v.w * 0.125f};
        __nv_bfloat16 hi[4], lo[4];
        #pragma unroll
        for (int t = 0; t < 4; t++) {
            hi[t] = __float2bfloat16_rn(vs[t]);
            lo[t] = __float2bfloat16_rn(vs[t] - __bfloat162float(hi[t]));
        }
        const int o = row * ST + c4;
        *(__nv_bfloat162*)(Qhi + o)     = __nv_bfloat162(hi[0], hi[1]);
        *(__nv_bfloat162*)(Qhi + o + 2) = __nv_bfloat162(hi[2], hi[3]);
        *(__nv_bfloat162*)(Qlo + o)     = __nv_bfloat162(lo[0], lo[1]);
        *(__nv_bfloat162*)(Qlo + o + 2) = __nv_bfloat162(lo[2], lo[3]);
    }

    // ---- prologue: K/V tile 0 ----
    {
        #pragma unroll
        for (int i = 0; i < 2; i++) {                 // bf16 planes: 8 elems / cp16
            int idx = tid + i * 256;                  // 0..511
            int row = idx >> 3;                       // 0..63
            int c8  = (idx & 7) * 8;                  // 0..56
            size_t go = basekv + (size_t)row * EQ + c8;
            cp16(smem_u32(Khs + row * ST + c8), g_khi16 + go);
            cp16(smem_u32(Kls + row * ST + c8), g_klo16 + go);
        }
        #pragma unroll
        for (int i = 0; i < 4; i++) {                 // V fp32: 4 elems / cp16
            int idx = tid + i * 256;
            int row = idx >> 4;
            int c4  = (idx & 15) * 4;
            cp16(smem_u32(Vsm + row * FS + c4), g_vtf + basekv + (size_t)row * EQ + c4);
        }
        cp_commit();
    }

    float m0 = -1e30f, m1 = -1e30f, l0 = 0.f, l1 = 0.f;
    float o[8][4];
    #pragma unroll
    for (int n = 0; n < 8; n++)
        #pragma unroll
        for (int r = 0; r < 4; r++) o[n][r] = 0.f;

    const int jmax = 2 * qt + 1;

    for (int j = 0; j <= jmax; j++) {
        cp_wait<0>();
        __syncthreads();

        if (j < jmax) {
            const int nb = (j + 1) & 1;
            #pragma unroll
            for (int i = 0; i < 2; i++) {
                int idx = tid + i * 256;
                int row = idx >> 3;
                int c8  = (idx & 7) * 8;
                size_t go = basekv + (size_t)((j + 1) * 64 + row) * EQ + c8;
                cp16(smem_u32(Khs + nb * KP + row * ST + c8), g_khi16 + go);
                cp16(smem_u32(Kls + nb * KP + row * ST + c8), g_klo16 + go);
            }
            #pragma unroll
            for (int i = 0; i < 4; i++) {
                int idx = tid + i * 256;
                int row = idx >> 4;
                int c4  = (idx & 15) * 4;
                cp16(smem_u32(Vsm + nb * VT + row * FS + c4),
                     g_vtf + basekv + (size_t)((j + 1) * 64 + row) * EQ + c4);
            }
            cp_commit();
        }

        const __nv_bfloat16* Kh = Khs + (j & 1) * KP;
        const __nv_bfloat16* Kl = Kls + (j & 1) * KP;
        const float* V = Vsm + (j & 1) * VT;

        // ---- S = Q K^T (split bf16, m16n8k16, 4 k-chunks) ----
        float s[8][4];
        #pragma unroll
        for (int n = 0; n < 8; n++)
            #pragma unroll
            for (int r = 0; r < 4; r++) s[n][r] = 0.f;

        #pragma unroll
        for (int ks = 0; ks < 4; ks++) {
            const int r0 = (wm + g) * ST + ks * 16 + 2 * q;
            const int r1 = (wm + g + 8) * ST + ks * 16 + 2 * q;
            uint32_t ahi[4], alo[4];
            ahi[0] = *(const uint32_t*)(Qhi + r0);
            ahi[1] = *(const uint32_t*)(Qhi + r1);
            ahi[2] = *(const uint32_t*)(Qhi + r0 + 8);
            ahi[3] = *(const uint32_t*)(Qhi + r1 + 8);
            alo[0] = *(const uint32_t*)(Qlo + r0);
            alo[1] = *(const uint32_t*)(Qlo + r1);
            alo[2] = *(const uint32_t*)(Qlo + r0 + 8);
            alo[3] = *(const uint32_t*)(Qlo + r1 + 8);

            uint32_t bhi[8][2], blo[8][2];
            #pragma unroll
            for (int n = 0; n < 8; n++) {
                const int kr = (n * 8 + g) * ST + ks * 16 + 2 * q;
                bhi[n][0] = *(const uint32_t*)(Kh + kr);
                bhi[n][1] = *(const uint32_t*)(Kh + kr + 8);
                blo[n][0] = *(const uint32_t*)(Kl + kr);
                blo[n][1] = *(const uint32_t*)(Kl + kr + 8);
            }
            #pragma unroll
            for (int n = 0; n < 8; n++) mma_bf16(s[n], ahi, bhi[n]);
            #pragma unroll
            for (int n = 0; n < 8; n++) mma_bf16(s[n], ahi, blo[n]);
            #pragma unroll
            for (int n = 0; n < 8; n++) mma_bf16(s[n], alo, bhi[n]);
        }

        // ---- causal mask ----
        if (j >= 2 * qt) {
            const int grow0 = qt * 128 + wm + g;
            const int grow1 = grow0 + 8;
            #pragma unroll
            for (int n = 0; n < 8; n++) {
                const int gc = j * 64 + n * 8 + 2 * q;
                if (gc     > grow0) s[n][0] = -1e30f;
                if (gc + 1 > grow0) s[n][1] = -1e30f;
                if (gc     > grow1) s[n][2] = -1e30f;
                if (gc + 1 > grow1) s[n][3] = -1e30f;
            }
        }

        // ---- online softmax ----
        float mt0 = -1e30f, mt1 = -1e30f;
        #pragma unroll
        for (int n = 0; n < 8; n++) {
            mt0 = fmaxf(mt0, fmaxf(s[n][0], s[n][1]));
            mt1 = fmaxf(mt1, fmaxf(s[n][2], s[n][3]));
        }
        mt0 = fmaxf(mt0, __shfl_xor_sync(0xffffffffu, mt0, 1));
        mt0 = fmaxf(mt0, __shfl_xor_sync(0xffffffffu, mt0, 2));
        mt1 = fmaxf(mt1, __shfl_xor_sync(0xffffffffu, mt1, 1));
        mt1 = fmaxf(mt1, __shfl_xor_sync(0xffffffffu, mt1, 2));

        const float mn0 = fmaxf(m0, mt0);
        const float mn1 = fmaxf(m1, mt1);
        const float a0 = __expf(m0 - mn0);
        const float a1 = __expf(m1 - mn1);
        float rs0 = 0.f, rs1 = 0.f;

        float* prow0 = Psm + (wm + g) * FS;
        float* prow1 = Psm + (wm + g + 8) * FS;
        #pragma unroll
        for (int n = 0; n < 8; n++) {
            float p00 = __expf(s[n][0] - mn0);
            float p01 = __expf(s[n][1] - mn0);
            float p10 = __expf(s[n][2] - mn1);
            float p11 = __expf(s[n][3] - mn1);
            rs0 += p00 + p01;
            rs1 += p10 + p11;
            prow0[n * 8 + 2 * q]     = tf32f(p00);
            prow0[n * 8 + 2 * q + 1] = tf32f(p01);
            prow1[n * 8 + 2 * q]     = tf32f(p10);
            prow1[n * 8 + 2 * q + 1] = tf32f(p11);
            o[n][0] *= a0; o[n][1] *= a0;
            o[n][2] *= a1; o[n][3] *= a1;
        }
        rs0 += __shfl_xor_sync(0xffffffffu, rs0, 1);
        rs0 += __shfl_xor_sync(0xffffffffu, rs0, 2);
        rs1 += __shfl_xor_sync(0xffffffffu, rs1, 1);
        rs1 += __shfl_xor_sync(0xffffffffu, rs1, 2);
        l0 = l0 * a0 + rs0;
        l1 = l1 * a1 + rs1;
        m0 = mn0;
        m1 = mn1;
        __syncwarp();

        // ---- O += P V (plain tf32) ----
        #pragma unroll
        for (int ks = 0; ks < 8; ks++) {
            const int c0 = ks * 8 + q, c1 = ks * 8 + q + 4;
            uint32_t pa[4];
            pa[0] = __float_as_uint(Psm[(wm + g) * FS + c0]);
            pa[1] = __float_as_uint(Psm[(wm + g + 8) * FS + c0]);
            pa[2] = __float_as_uint(Psm[(wm + g) * FS + c1]);
            pa[3] = __float_as_uint(Psm[(wm + g + 8) * FS + c1]);
            uint32_t vb[8][2];
            #pragma unroll
            for (int n = 0; n < 8; n++) {
                vb[n][0] = __float_as_uint(V[c0 * FS + n * 8 + g]);
                vb[n][1] = __float_as_uint(V[c1 * FS + n * 8 + g]);
            }
            #pragma unroll
            for (int n = 0; n < 8; n++) mma_tf32(o[n], pa, vb[n]);
        }
    }

    // ---- epilogue: write y pre-converted to tf32 bits ----
    const float inv0 = 1.f / l0;
    const float inv1 = 1.f / l1;
    const size_t row0 = (size_t)b * TQ + qt * 128 + wm + g;
    #pragma unroll
    for (int n = 0; n < 8; n++) {
        const int col = h * DQ + n * 8 + 2 * q;
        float2 v0 = make_float2(tf32f(o[n][0] * inv0), tf32f(o[n][1] * inv0));
        float2 v1 = make_float2(tf32f(o[n][2] * inv1), tf32f(o[n][3] * inv1));
        *(float2*)(g_y + row0 * EQ + col) = v0;
        *(float2*)(g_y + (row0 + 8) * EQ + col) = v1;
    }
}

// ---------------------------------------------------------------------------
extern "C" void kernel_launch(void* const* d_in, const int* in_sizes, int n_in,
                              void* d_out, int out_size)
{
    const float* x     = (const float*)d_in[0];
    const float* Wqkv  = (const float*)d_in[1];
    const float* bqkv  = (const float*)d_in[2];
    const float* Wproj = (const float*)d_in[3];
    const float* bproj = (const float*)d_in[4];
    float* out = (float*)d_out;

    float *qkv, *y, *xtf, *wqkv_tf, *wproj_tf;
    cudaGetSymbolAddress((void**)&qkv, g_qkv);
    cudaGetSymbolAddress((void**)&y, g_y);
    cudaGetSymbolAddress((void**)&xtf, g_xtf);
    cudaGetSymbolAddress((void**)&wqkv_tf, g_wqkv_tf);
    cudaGetSymbolAddress((void**)&wproj_tf, g_wproj_tf);

    const int M = BQ * TQ;  // 8192

    // 0) tf32 prepasses for GEMM operands
    cvt_tf32_kernel<<<592, 256>>>((const float4*)x, (float4*)xtf, M * EQ / 4);
    cvt_tf32_kernel<<<592, 256>>>((const float4*)Wqkv, (float4*)wqkv_tf, EQ * 3 * EQ / 4);
    cvt_tf32_kernel<<<592, 256>>>((const float4*)Wproj, (float4*)wproj_tf, EQ * EQ / 4);

    // 1) QKV GEMM (tf32 tensor cores)
    {
        dim3 grid(3 * EQ / 128, M / 128);
        gemm_tf32_bias_kernel<<<grid, 256>>>(xtf, wqkv_tf, bqkv, qkv, M, 3 * EQ, EQ);
    }

    // 1.5) split K -> bf16 (hi, lo) planes, convert V -> tf32
    split_kv_kernel<<<592, 256>>>(qkv);

    // 2) Flash attention (split-bf16 S, tf32 PV) -> g_y (tf32 bits)
    {
        const int smem_bytes =
            (2 * QP + 4 * KP) * 2 + (2 * VT + 128 * FS) * 4;  // 143360
        cudaFuncSetAttribute(flash_attn_mma_kernel,
                             cudaFuncAttributeMaxDynamicSharedMemorySize, smem_bytes);
        dim3 grid(TQ / 128, HQ, BQ);
        flash_attn_mma_kernel<<<grid, 256, smem_bytes>>>(qkv);
    }

    // 3) Proj GEMM (tf32 tensor cores) -> d_out
    {
        dim3 grid(EQ / 128, M / 128);
        gemm_tf32_bias_kernel<<<grid, 256>>>(y, wproj_tf, bproj, out, M, EQ, EQ);
    }

    (void)in_sizes; (void)n_in; (void)out_size;
}

// round 13
// speedup vs baseline: 3.7257x; 1.2185x over previous
#include <cuda_runtime.h>
#include <cuda_bf16.h>
#include <cuda_fp16.h>
#include <math.h>
#include <stdint.h>

#define BQ 4
#define TQ 2048
#define EQ 1024
#define HQ 16
#define DQ 64

// Scratch (allocation-free rule: __device__ globals)
__device__ float g_qkv[(size_t)BQ * TQ * 3 * EQ];   // [8192, 3072] fp32
__device__ float g_y[(size_t)BQ * TQ * EQ];         // [8192, 1024] tf32 bits
__device__ float g_xtf[(size_t)BQ * TQ * EQ];       // x in tf32 bits
__device__ float g_wqkv_tf[(size_t)EQ * 3 * EQ];    // W_qkv tf32 bits
__device__ float g_wproj_tf[(size_t)EQ * EQ];       // W_proj tf32 bits
__device__ __nv_bfloat16 g_khi16[(size_t)BQ * TQ * EQ];  // K hi bf16, dense [B*T, E]
__device__ __nv_bfloat16 g_klo16[(size_t)BQ * TQ * EQ];  // K lo bf16
__device__ __half g_vt[(size_t)BQ * HQ * DQ * TQ];       // V^T fp16: [b][h][d][key]

// ---------------------------------------------------------------------------
// helpers
// ---------------------------------------------------------------------------
__device__ __forceinline__ uint32_t smem_u32(const void* p) {
    return (uint32_t)__cvta_generic_to_shared(p);
}

__device__ __forceinline__ void cp16(uint32_t dst, const void* src) {
    asm volatile("cp.async.cg.shared.global [%0], [%1], 16;\n" ::"r"(dst), "l"(src));
}

__device__ __forceinline__ void cp_commit() {
    asm volatile("cp.async.commit_group;\n");
}

template <int N>
__device__ __forceinline__ void cp_wait() {
    asm volatile("cp.async.wait_group %0;\n" ::"n"(N));
}

__device__ __forceinline__ uint32_t f2tf32(float f) {
    uint32_t u;
    asm("cvt.rna.tf32.f32 %0, %1;\n" : "=r"(u) : "f"(f));
    return u;
}

__device__ __forceinline__ float tf32f(float f) {
    return __uint_as_float(f2tf32(f));
}

__device__ __forceinline__ void mma_tf32(float* c, const uint32_t* a, const uint32_t* b) {
    asm volatile(
        "mma.sync.aligned.m16n8k8.row.col.f32.tf32.tf32.f32 "
        "{%0,%1,%2,%3},{%4,%5,%6,%7},{%8,%9},{%0,%1,%2,%3};\n"
        : "+f"(c[0]), "+f"(c[1]), "+f"(c[2]), "+f"(c[3])
        : "r"(a[0]), "r"(a[1]), "r"(a[2]), "r"(a[3]), "r"(b[0]), "r"(b[1]));
}

__device__ __forceinline__ void mma_bf16(float* c, const uint32_t* a, const uint32_t* b) {
    asm volatile(
        "mma.sync.aligned.m16n8k16.row.col.f32.bf16.bf16.f32 "
        "{%0,%1,%2,%3},{%4,%5,%6,%7},{%8,%9},{%0,%1,%2,%3};\n"
        : "+f"(c[0]), "+f"(c[1]), "+f"(c[2]), "+f"(c[3])
        : "r"(a[0]), "r"(a[1]), "r"(a[2]), "r"(a[3]), "r"(b[0]), "r"(b[1]));
}

__device__ __forceinline__ void mma_f16(float* c, const uint32_t* a, const uint32_t* b) {
    asm volatile(
        "mma.sync.aligned.m16n8k16.row.col.f32.f16.f16.f32 "
        "{%0,%1,%2,%3},{%4,%5,%6,%7},{%8,%9},{%0,%1,%2,%3};\n"
        : "+f"(c[0]), "+f"(c[1]), "+f"(c[2]), "+f"(c[3])
        : "r"(a[0]), "r"(a[1]), "r"(a[2]), "r"(a[3]), "r"(b[0]), "r"(b[1]));
}

// ---------------------------------------------------------------------------
// Prepass: elementwise tf32 conversion
// ---------------------------------------------------------------------------
__global__ __launch_bounds__(256) void cvt_tf32_kernel(
    const float4* __restrict__ src, float4* __restrict__ dst, int n4)
{
    int i = blockIdx.x * 256 + threadIdx.x;
    int stride = gridDim.x * 256;
    for (; i < n4; i += stride) {
        float4 v = src[i];
        v.x = tf32f(v.x); v.y = tf32f(v.y); v.z = tf32f(v.z); v.w = tf32f(v.w);
        dst[i] = v;
    }
}

// ---------------------------------------------------------------------------
// Prepass: K -> (hi, lo) bf16 planes. qkv layout [B*T, 3E].
// ---------------------------------------------------------------------------
__global__ __launch_bounds__(256) void split_k_kernel(const float* __restrict__ qkv)
{
    const int n4 = BQ * TQ * EQ / 4;
    int i = blockIdx.x * 256 + threadIdx.x;
    int stride = gridDim.x * 256;
    for (; i < n4; i += stride) {
        int row = i / (EQ / 4);
        int c4 = (i % (EQ / 4)) * 4;
        const float* kp = qkv + (size_t)row * (3 * EQ) + EQ + c4;
        float4 k = *(const float4*)kp;

        __nv_bfloat16 hx = __float2bfloat16_rn(k.x);
        __nv_bfloat16 hy = __float2bfloat16_rn(k.y);
        __nv_bfloat16 hz = __float2bfloat16_rn(k.z);
        __nv_bfloat16 hw = __float2bfloat16_rn(k.w);
        __nv_bfloat16 lx = __float2bfloat16_rn(k.x - __bfloat162float(hx));
        __nv_bfloat16 ly = __float2bfloat16_rn(k.y - __bfloat162float(hy));
        __nv_bfloat16 lz = __float2bfloat16_rn(k.z - __bfloat162float(hz));
        __nv_bfloat16 lw = __float2bfloat16_rn(k.w - __bfloat162float(hw));

        size_t o = (size_t)row * EQ + c4;
        *(__nv_bfloat162*)(g_khi16 + o)     = __nv_bfloat162(hx, hy);
        *(__nv_bfloat162*)(g_khi16 + o + 2) = __nv_bfloat162(hz, hw);
        *(__nv_bfloat162*)(g_klo16 + o)     = __nv_bfloat162(lx, ly);
        *(__nv_bfloat162*)(g_klo16 + o + 2) = __nv_bfloat162(lz, lw);
    }
}

// ---------------------------------------------------------------------------
// Prepass: V -> fp16 transposed per (b,h): g_vt[b][h][d][key].
// grid (T/64, H, B), 256 threads.
// ---------------------------------------------------------------------------
__global__ __launch_bounds__(256) void vt_kernel(const float* __restrict__ qkv)
{
    const int kt = blockIdx.x, h = blockIdx.y, b = blockIdx.z;
    const int tid = threadIdx.x;
    const int key4 = (tid & 15) * 4;
    const size_t vbase = (size_t)b * TQ * (3 * EQ) + 2 * EQ + h * DQ;
    const size_t obase = ((size_t)(b * HQ + h) * DQ) * TQ + kt * 64 + key4;
    const size_t rs = 3 * EQ;
    #pragma unroll
    for (int d = tid >> 4; d < DQ; d += 16) {
        const float* src = qkv + vbase + (size_t)(kt * 64 + key4) * rs + d;
        float v0 = src[0];
        float v1 = src[rs];
        float v2 = src[2 * rs];
        float v3 = src[3 * rs];
        __half2 h0 = __floats2half2_rn(v0, v1);
        __half2 h1 = __floats2half2_rn(v2, v3);
        uint2 u;
        u.x = *(uint32_t*)&h0;
        u.y = *(uint32_t*)&h1;
        *(uint2*)(g_vt + obase + (size_t)d * TQ) = u;
    }
}

// ---------------------------------------------------------------------------
// tf32 tensor-core GEMM + bias (operands pre-converted tf32 bits). Unchanged.
// ---------------------------------------------------------------------------
#define GK 16
#define ASTRIDE 20
#define BSTRIDE 136

__global__ __launch_bounds__(256) void gemm_tf32_bias_kernel(
    const float* __restrict__ A, const float* __restrict__ W,
    const float* __restrict__ bias, float* __restrict__ C,
    int M, int N, int K)
{
    __shared__ float As[2][128][ASTRIDE];
    __shared__ float Bs[2][GK][BSTRIDE];

    const int tid  = threadIdx.x;
    const int lane = tid & 31;
    const int warp = tid >> 5;
    const int wm   = (warp >> 1) * 32;
    const int wn   = (warp & 1) * 64;
    const int g    = lane >> 2;
    const int q    = lane & 3;

    const int bm = blockIdx.y * 128;
    const int bn = blockIdx.x * 128;

    float acc[2][8][4];
    #pragma unroll
    for (int i = 0; i < 2; i++)
        #pragma unroll
        for (int j = 0; j < 8; j++)
            #pragma unroll
            for (int r = 0; r < 4; r++) acc[i][j][r] = 0.f;

    const int nt = K / GK;

    {
        #pragma unroll
        for (int i = 0; i < 2; i++) {
            int j = tid + i * 256;
            int row = j >> 2, c4 = (j & 3) * 4;
            cp16(smem_u32(&As[0][row][c4]), A + (size_t)(bm + row) * K + c4);
        }
        #pragma unroll
        for (int i = 0; i < 2; i++) {
            int j = tid + i * 256;
            int kr = j >> 5, nc = (j & 31) * 4;
            cp16(smem_u32(&Bs[0][kr][nc]), W + (size_t)kr * N + bn + nc);
        }
        cp_commit();
    }

    for (int kt = 0; kt < nt; kt++) {
        const int buf = kt & 1;
        if (kt + 1 < nt) {
            const int nb = buf ^ 1;
            const int k0 = (kt + 1) * GK;
            #pragma unroll
            for (int i = 0; i < 2; i++) {
                int j = tid + i * 256;
                int row = j >> 2, c4 = (j & 3) * 4;
                cp16(smem_u32(&As[nb][row][c4]), A + (size_t)(bm + row) * K + k0 + c4);
            }
            #pragma unroll
            for (int i = 0; i < 2; i++) {
                int j = tid + i * 256;
                int kr = j >> 5, nc = (j & 31) * 4;
                cp16(smem_u32(&Bs[nb][kr][nc]), W + (size_t)(k0 + kr) * N + bn + nc);
            }
            cp_commit();
            cp_wait<1>();
        } else {
            cp_wait<0>();
        }
        __syncthreads();

        #pragma unroll
        for (int ks = 0; ks < GK; ks += 8) {
            uint32_t afr[2][4];
            #pragma unroll
            for (int i = 0; i < 2; i++) {
                int r0 = wm + i * 16 + g;
                afr[i][0] = __float_as_uint(As[buf][r0][ks + q]);
                afr[i][1] = __float_as_uint(As[buf][r0 + 8][ks + q]);
                afr[i][2] = __float_as_uint(As[buf][r0][ks + q + 4]);
                afr[i][3] = __float_as_uint(As[buf][r0 + 8][ks + q + 4]);
            }
            uint32_t bfr[8][2];
            #pragma unroll
            for (int j = 0; j < 8; j++) {
                int n0 = wn + j * 8 + g;
                bfr[j][0] = __float_as_uint(Bs[buf][ks + q][n0]);
                bfr[j][1] = __float_as_uint(Bs[buf][ks + q + 4][n0]);
            }
            #pragma unroll
            for (int i = 0; i < 2; i++)
                #pragma unroll
                for (int j = 0; j < 8; j++)
                    mma_tf32(acc[i][j], afr[i], bfr[j]);
        }
        __syncthreads();
    }

    #pragma unroll
    for (int i = 0; i < 2; i++) {
        #pragma unroll
        for (int j = 0; j < 8; j++) {
            int row = bm + wm + i * 16 + g;
            int col = bn + wn + j * 8 + 2 * q;
            float bx = bias[col], by = bias[col + 1];
            float2 v0 = make_float2(acc[i][j][0] + bx, acc[i][j][1] + by);
            float2 v1 = make_float2(acc[i][j][2] + bx, acc[i][j][3] + by);
            *(float2*)(C + (size_t)row * N + col) = v0;
            *(float2*)(C + (size_t)(row + 8) * N + col) = v1;
        }
    }
}

// ---------------------------------------------------------------------------
// Flash attention (causal).
// S = Q K^T via split-bf16 m16n8k16 (3 MMAs per k16).
// P stays in registers as fp16 (S C-fragment == PV A-fragment layout).
// PV via m16n8k16 fp16 against V^T fp16 smem tiles (conflict-free b-frags).
// 2 CTAs/SM (90 KB smem). KV tiles 64 rows, double-buffered.
// ---------------------------------------------------------------------------
#define ST 72                  // bf16 smem row stride (elements)
#define QP (128 * ST)          // one Q bf16 plane (elements)
#define KP (64 * ST)           // one K bf16 plane per buffer (elements)
#define VT2 (64 * ST)          // one V^T fp16 buffer (elements)

__global__ __launch_bounds__(256, 2) void flash_attn_mma_kernel(
    const float* __restrict__ qkv)
{
    extern __shared__ char smraw[];
    __nv_bfloat16* Qhi = (__nv_bfloat16*)smraw;      // [128][ST]
    __nv_bfloat16* Qlo = Qhi + QP;                   // [128][ST]
    __nv_bfloat16* Khs = Qlo + QP;                   // [2][64][ST]
    __nv_bfloat16* Kls = Khs + 2 * KP;               // [2][64][ST]
    __half* Vts = (__half*)(Kls + 2 * KP);           // [2][64][ST] V^T (d rows, key cols)

    const int qt = blockIdx.x;
    const int h  = blockIdx.y;
    const int b  = blockIdx.z;
    const int tid  = threadIdx.x;
    const int lane = tid & 31;
    const int warp = tid >> 5;
    const int g = lane >> 2;
    const int q = lane & 3;
    const int wm = warp * 16;

    const size_t rs = 3 * EQ;
    const size_t baseq = (size_t)b * TQ * rs;
    const size_t basek = (size_t)b * TQ * EQ + h * DQ;          // K planes [B*T, E]
    const size_t basev = ((size_t)(b * HQ + h) * DQ) * TQ;      // Vt [d][key]

    // ---- Load Q tile [128, 64], scale, split to bf16 hi/lo planes ----
    #pragma unroll
    for (int i = 0; i < 8; i++) {
        int idx = tid + i * 256;
        int row = idx >> 4;
        int c4  = (idx & 15) * 4;
        const float* src = qkv + baseq + (size_t)(qt * 128 + row) * rs + h * DQ + c4;
        float4 v = *(const float4*)src;
        float vs[4] = {v.x * 0.125f, v.y * 0.125f, v.z * 0.125f, v.w * 0.125f};
        __nv_bfloat16 hi[4], lo[4];
        #pragma unroll
        for (int t = 0; t < 4; t++) {
            hi[t] = __float2bfloat16_rn(vs[t]);
            lo[t] = __float2bfloat16_rn(vs[t] - __bfloat162float(hi[t]));
        }
        const int o = row * ST + c4;
        *(__nv_bfloat162*)(Qhi + o)     = __nv_bfloat162(hi[0], hi[1]);
        *(__nv_bfloat162*)(Qhi + o + 2) = __nv_bfloat162(hi[2], hi[3]);
        *(__nv_bfloat162*)(Qlo + o)     = __nv_bfloat162(lo[0], lo[1]);
        *(__nv_bfloat162*)(Qlo + o + 2) = __nv_bfloat162(lo[2], lo[3]);
    }

    // ---- prologue: K/V tile 0 ----
    {
        #pragma unroll
        for (int i = 0; i < 2; i++) {
            int idx = tid + i * 256;                  // 0..511
            int row = idx >> 3;                       // 0..63
            int c8  = (idx & 7) * 8;                  // 0..56
            size_t go = basek + (size_t)row * EQ + c8;
            cp16(smem_u32(Khs + row * ST + c8), g_khi16 + go);
            cp16(smem_u32(Kls + row * ST + c8), g_klo16 + go);
            cp16(smem_u32(Vts + row * ST + c8), g_vt + basev + (size_t)row * TQ + c8);
        }
        cp_commit();
    }

    float m0 = -1e30f, m1 = -1e30f, l0 = 0.f, l1 = 0.f;
    float o[8][4];
    #pragma unroll
    for (int n = 0; n < 8; n++)
        #pragma unroll
        for (int r = 0; r < 4; r++) o[n][r] = 0.f;

    const int jmax = 2 * qt + 1;

    for (int j = 0; j <= jmax; j++) {
        cp_wait<0>();
        __syncthreads();

        if (j < jmax) {
            const int nb = (j + 1) & 1;
            #pragma unroll
            for (int i = 0; i < 2; i++) {
                int idx = tid + i * 256;
                int row = idx >> 3;
                int c8  = (idx & 7) * 8;
                size_t go = basek + (size_t)((j + 1) * 64 + row) * EQ + c8;
                cp16(smem_u32(Khs + nb * KP + row * ST + c8), g_khi16 + go);
                cp16(smem_u32(Kls + nb * KP + row * ST + c8), g_klo16 + go);
                cp16(smem_u32(Vts + nb * VT2 + row * ST + c8),
                     g_vt + basev + (size_t)row * TQ + (j + 1) * 64 + c8);
            }
            cp_commit();
        }

        const __nv_bfloat16* Kh = Khs + (j & 1) * KP;
        const __nv_bfloat16* Kl = Kls + (j & 1) * KP;
        const __half* Vt = Vts + (j & 1) * VT2;

        // ---- S = Q K^T (split bf16, m16n8k16, 4 k-chunks) ----
        float s[8][4];
        #pragma unroll
        for (int n = 0; n < 8; n++)
            #pragma unroll
            for (int r = 0; r < 4; r++) s[n][r] = 0.f;

        #pragma unroll
        for (int ks = 0; ks < 4; ks++) {
            const int r0 = (wm + g) * ST + ks * 16 + 2 * q;
            const int r1 = (wm + g + 8) * ST + ks * 16 + 2 * q;
            uint32_t ahi[4], alo[4];
            ahi[0] = *(const uint32_t*)(Qhi + r0);
            ahi[1] = *(const uint32_t*)(Qhi + r1);
            ahi[2] = *(const uint32_t*)(Qhi + r0 + 8);
            ahi[3] = *(const uint32_t*)(Qhi + r1 + 8);
            alo[0] = *(const uint32_t*)(Qlo + r0);
            alo[1] = *(const uint32_t*)(Qlo + r1);
            alo[2] = *(const uint32_t*)(Qlo + r0 + 8);
            alo[3] = *(const uint32_t*)(Qlo + r1 + 8);

            uint32_t bhi[8][2], blo[8][2];
            #pragma unroll
            for (int n = 0; n < 8; n++) {
                const int kr = (n * 8 + g) * ST + ks * 16 + 2 * q;
                bhi[n][0] = *(const uint32_t*)(Kh + kr);
                bhi[n][1] = *(const uint32_t*)(Kh + kr + 8);
                blo[n][0] = *(const uint32_t*)(Kl + kr);
                blo[n][1] = *(const uint32_t*)(Kl + kr + 8);
            }
            #pragma unroll
            for (int n = 0; n < 8; n++) mma_bf16(s[n], ahi, bhi[n]);
            #pragma unroll
            for (int n = 0; n < 8; n++) mma_bf16(s[n], ahi, blo[n]);
            #pragma unroll
            for (int n = 0; n < 8; n++) mma_bf16(s[n], alo, bhi[n]);
        }

        // ---- causal mask ----
        if (j >= 2 * qt) {
            const int grow0 = qt * 128 + wm + g;
            const int grow1 = grow0 + 8;
            #pragma unroll
            for (int n = 0; n < 8; n++) {
                const int gc = j * 64 + n * 8 + 2 * q;
                if (gc     > grow0) s[n][0] = -1e30f;
                if (gc + 1 > grow0) s[n][1] = -1e30f;
                if (gc     > grow1) s[n][2] = -1e30f;
                if (gc + 1 > grow1) s[n][3] = -1e30f;
            }
        }

        // ---- online softmax; P packed to fp16 registers ----
        float mt0 = -1e30f, mt1 = -1e30f;
        #pragma unroll
        for (int n = 0; n < 8; n++) {
            mt0 = fmaxf(mt0, fmaxf(s[n][0], s[n][1]));
            mt1 = fmaxf(mt1, fmaxf(s[n][2], s[n][3]));
        }
        mt0 = fmaxf(mt0, __shfl_xor_sync(0xffffffffu, mt0, 1));
        mt0 = fmaxf(mt0, __shfl_xor_sync(0xffffffffu, mt0, 2));
        mt1 = fmaxf(mt1, __shfl_xor_sync(0xffffffffu, mt1, 1));
        mt1 = fmaxf(mt1, __shfl_xor_sync(0xffffffffu, mt1, 2));

        const float mn0 = fmaxf(m0, mt0);
        const float mn1 = fmaxf(m1, mt1);
        const float a0 = __expf(m0 - mn0);
        const float a1 = __expf(m1 - mn1);
        float rs0 = 0.f, rs1 = 0.f;

        uint32_t pA[8], pB[8];   // rows g / g+8, fp16x2 pairs per n8-tile
        #pragma unroll
        for (int n = 0; n < 8; n++) {
            float p00 = __expf(s[n][0] - mn0);
            float p01 = __expf(s[n][1] - mn0);
            float p10 = __expf(s[n][2] - mn1);
            float p11 = __expf(s[n][3] - mn1);
            rs0 += p00 + p01;
            rs1 += p10 + p11;
            __half2 h0 = __floats2half2_rn(p00, p01);
            __half2 h1 = __floats2half2_rn(p10, p11);
            pA[n] = *(uint32_t*)&h0;
            pB[n] = *(uint32_t*)&h1;
            o[n][0] *= a0; o[n][1] *= a0;
            o[n][2] *= a1; o[n][3] *= a1;
        }
        rs0 += __shfl_xor_sync(0xffffffffu, rs0, 1);
        rs0 += __shfl_xor_sync(0xffffffffu, rs0, 2);
        rs1 += __shfl_xor_sync(0xffffffffu, rs1, 1);
        rs1 += __shfl_xor_sync(0xffffffffu, rs1, 2);
        l0 = l0 * a0 + rs0;
        l1 = l1 * a1 + rs1;
        m0 = mn0;
        m1 = mn1;

        // ---- O += P V (fp16 m16n8k16, P from registers, V^T from smem) ----
        #pragma unroll
        for (int c = 0; c < 4; c++) {
            uint32_t pa[4] = {pA[2 * c], pB[2 * c], pA[2 * c + 1], pB[2 * c + 1]};
            uint32_t vb[8][2];
            #pragma unroll
            for (int n = 0; n < 8; n++) {
                const int vr = (n * 8 + g) * ST + c * 16 + 2 * q;
                vb[n][0] = *(const uint32_t*)(Vt + vr);
                vb[n][1] = *(const uint32_t*)(Vt + vr + 8);
            }
            #pragma unroll
            for (int n = 0; n < 8; n++) mma_f16(o[n], pa, vb[n]);
        }
    }

    // ---- epilogue: write y pre-converted to tf32 bits ----
    const float inv0 = 1.f / l0;
    const float inv1 = 1.f / l1;
    const size_t row0 = (size_t)b * TQ + qt * 128 + wm + g;
    #pragma unroll
    for (int n = 0; n < 8; n++) {
        const int col = h * DQ + n * 8 + 2 * q;
        float2 v0 = make_float2(tf32f(o[n][0] * inv0), tf32f(o[n][1] * inv0));
        float2 v1 = make_float2(tf32f(o[n][2] * inv1), tf32f(o[n][3] * inv1));
        *(float2*)(g_y + row0 * EQ + col) = v0;
        *(float2*)(g_y + (row0 + 8) * EQ + col) = v1;
    }
}

// ---------------------------------------------------------------------------
extern "C" void kernel_launch(void* const* d_in, const int* in_sizes, int n_in,
                              void* d_out, int out_size)
{
    const float* x     = (const float*)d_in[0];
    const float* Wqkv  = (const float*)d_in[1];
    const float* bqkv  = (const float*)d_in[2];
    const float* Wproj = (const float*)d_in[3];
    const float* bproj = (const float*)d_in[4];
    float* out = (float*)d_out;

    float *qkv, *y, *xtf, *wqkv_tf, *wproj_tf;
    cudaGetSymbolAddress((void**)&qkv, g_qkv);
    cudaGetSymbolAddress((void**)&y, g_y);
    cudaGetSymbolAddress((void**)&xtf, g_xtf);
    cudaGetSymbolAddress((void**)&wqkv_tf, g_wqkv_tf);
    cudaGetSymbolAddress((void**)&wproj_tf, g_wproj_tf);

    const int M = BQ * TQ;  // 8192

    // 0) tf32 prepasses for GEMM operands
    cvt_tf32_kernel<<<592, 256>>>((const float4*)x, (float4*)xtf, M * EQ / 4);
    cvt_tf32_kernel<<<592, 256>>>((const float4*)Wqkv, (float4*)wqkv_tf, EQ * 3 * EQ / 4);
    cvt_tf32_kernel<<<592, 256>>>((const float4*)Wproj, (float4*)wproj_tf, EQ * EQ / 4);

    // 1) QKV GEMM (tf32 tensor cores)
    {
        dim3 grid(3 * EQ / 128, M / 128);
        gemm_tf32_bias_kernel<<<grid, 256>>>(xtf, wqkv_tf, bqkv, qkv, M, 3 * EQ, EQ);
    }

    // 1.5) K -> bf16 (hi, lo) planes; V -> fp16 transposed
    split_k_kernel<<<592, 256>>>(qkv);
    {
        dim3 grid(TQ / 64, HQ, BQ);
        vt_kernel<<<grid, 256>>>(qkv);
    }

    // 2) Flash attention (split-bf16 S, fp16 register-P PV) -> g_y (tf32 bits)
    {
        const int smem_bytes = (2 * QP + 4 * KP + 2 * VT2) * 2;  // 92160
        cudaFuncSetAttribute(flash_attn_mma_kernel,
                             cudaFuncAttributeMaxDynamicSharedMemorySize, smem_bytes);
        dim3 grid(TQ / 128, HQ, BQ);
        flash_attn_mma_kernel<<<grid, 256, smem_bytes>>>(qkv);
    }

    // 3) Proj GEMM (tf32 tensor cores) -> d_out
    {
        dim3 grid(EQ / 128, M / 128);
        gemm_tf32_bias_kernel<<<grid, 256>>>(y, wproj_tf, bproj, out, M, EQ, EQ);
    }

    (void)in_sizes; (void)n_in; (void)out_size;
}